// round 5
// baseline (speedup 1.0000x reference)
#include <cuda_runtime.h>
#include <math.h>

#define N_B      8192
#define CONT     62
#define EMB      16
#define FEAT     94
#define FPAD     96
#define KNB      64
#define NH       4
#define NOUT     16
#define HO       64
#define NTHREADS 256
#define FSTR     100   // sFeat row stride in floats

// ---------------- folded-weight scratch (written by prep_kernel each launch) ----
__device__ float g_wd2[NH * FPAD];     // Wd[h] @ a2[h], f-padded with zeros
__device__ float g_vch[NH * FPAD];     // Wc[h] @ a1[h], f-padded with zeros
__device__ float g_ech[NH];            // bc·a1 + ab + bd·a2
__device__ float g_Wdp[FPAD * HO];     // Wd as [f][h*16+o], zero rows f>=94
__device__ float g_Wfus[(2 * FEAT + HO) * 64];  // 252x64: [W2a; W2b; W1@W2c]
__device__ float g_b2f[64];            // b2 + b1@W2c

__global__ __launch_bounds__(NTHREADS) void prep_kernel(
    const float* __restrict__ Wc, const float* __restrict__ bc,
    const float* __restrict__ Wd, const float* __restrict__ bd,
    const float* __restrict__ aW, const float* __restrict__ ab,
    const float* __restrict__ W1, const float* __restrict__ b1,
    const float* __restrict__ W2, const float* __restrict__ b2)
{
    const int tid = threadIdx.x;

    for (int idx = tid; idx < NH * FPAD; idx += NTHREADS) {
        int h = idx / FPAD, f = idx % FPAD;
        float s2 = 0.f, s1 = 0.f;
        if (f < FEAT) {
            #pragma unroll
            for (int o = 0; o < NOUT; o++) {
                s2 += Wd[(h * FEAT + f) * NOUT + o] * aW[h * 2 * NOUT + NOUT + o];
                s1 += Wc[(h * FEAT + f) * NOUT + o] * aW[h * 2 * NOUT + o];
            }
        }
        g_wd2[idx] = s2;
        g_vch[idx] = s1;
    }
    if (tid < NH) {
        float s = ab[tid];
        #pragma unroll
        for (int o = 0; o < NOUT; o++) {
            s += bc[tid * NOUT + o] * aW[tid * 2 * NOUT + o];
            s += bd[tid * NOUT + o] * aW[tid * 2 * NOUT + NOUT + o];
        }
        g_ech[tid] = s;
    }
    for (int idx = tid; idx < FPAD * HO; idx += NTHREADS) {
        int f = idx >> 6, ho = idx & 63;
        g_Wdp[idx] = (f < FEAT) ? Wd[((ho >> 4) * FEAT + f) * NOUT + (ho & 15)] : 0.f;
    }
    for (int idx = tid; idx < (2 * FEAT + HO) * 64; idx += NTHREADS) {
        int r = idx >> 6, j = idx & 63;
        float v;
        if (r < 2 * FEAT) {
            v = W2[r * 64 + j];
        } else {
            int i = r - 2 * FEAT;
            float s = 0.f;
            #pragma unroll
            for (int t = 0; t < NOUT; t++)
                s += W1[i * NOUT + t] * W2[(2 * FEAT + t) * 64 + j];
            v = s;
        }
        g_Wfus[idx] = v;
    }
    if (tid < 64) {
        float s = b2[tid];
        #pragma unroll
        for (int t = 0; t < NOUT; t++)
            s += b1[t] * W2[(2 * FEAT + t) * 64 + tid];
        g_b2f[tid] = s;
    }
}

// ---------------- main fused kernel: one CTA per batch element -------------------
__global__ __launch_bounds__(NTHREADS) void gat_kernel(
    const float* __restrict__ combin_cont,
    const int*   __restrict__ combin_cat,
    const float* __restrict__ device_cont,
    const int*   __restrict__ device_cat,
    const int*   __restrict__ combin_idx,
    const int*   __restrict__ device_idx,
    const int*   __restrict__ neighbor_idx,
    const float* __restrict__ ce0,
    const float* __restrict__ ce1,
    const float* __restrict__ de0,
    const float* __restrict__ de1,
    const float* __restrict__ bd,
    const float* __restrict__ W3,
    const float* __restrict__ b3,
    const float* __restrict__ W4,
    const float* __restrict__ b4,
    float* __restrict__ out)
{
    __shared__ __align__(16) float sFeat[KNB * FSTR];     // 25600B
    __shared__ __align__(16) float sWd2[NH * FPAD];       // [h][f]
    __shared__ __align__(16) float sEp[4 * NH * KNB];     // S1 partials [c][h][k]
    __shared__ __align__(16) float sMp[2 * NH * FPAD];    // S2 partials [half][h][f]
    __shared__ float sE[NH * KNB];                        // attn [h][k]
    __shared__ float sEbase[NH];
    __shared__ float sComb[FPAD];
    __shared__ float sDev[FPAD];
    __shared__ float sHO[HO];
    __shared__ float sX2[64];
    __shared__ float sPA[64];
    __shared__ float sPB0[64];
    __shared__ float sPB1[64];
    __shared__ float sP2[4 * 32];
    __shared__ int   sNid[KNB];
    __shared__ int   sCat0[KNB];
    __shared__ int   sCat1[KNB];

    const int b    = blockIdx.x;
    const int tid  = threadIdx.x;
    const int lane = tid & 31;

    // ---- Prologue A: independent loads ----
    if (tid < 96) {
        reinterpret_cast<float4*>(sWd2)[tid] = reinterpret_cast<const float4*>(g_wd2)[tid];
    }
    if (tid < KNB) {
        sNid[tid] = neighbor_idx[b * KNB + tid];
    } else if (tid >= 96 && tid < 96 + FEAT) {
        int f = tid - 96;
        int ci = combin_idx[b];
        float v;
        if (f < CONT)            v = combin_cont[ci * CONT + f];
        else if (f < CONT + EMB) v = ce0[combin_cat[2 * ci]     * EMB + (f - CONT)];
        else                     v = ce1[combin_cat[2 * ci + 1] * EMB + (f - CONT - EMB)];
        sComb[f] = v;
    } else if (tid >= 192 && tid < 192 + 62) {
        int f = tid - 192;
        int di = device_idx[b];
        sDev[f] = device_cont[di * CONT + f];
    } else if (tid >= 64 && tid < 96) {
        int f = tid - 64 + CONT;   // f in [62,94)
        int di = device_idx[b];
        float v;
        if (f < CONT + EMB) v = de0[device_cat[2 * di]     * EMB + (f - CONT)];
        else                v = de1[device_cat[2 * di + 1] * EMB + (f - CONT - EMB)];
        sDev[f] = v;
    }
    __syncthreads();

    // ---- Prologue B: neighbor cat ids + e_base ----
    if (tid < KNB) {
        sCat0[tid] = device_cat[2 * sNid[tid]];
    } else if (tid < 2 * KNB) {
        sCat1[tid - KNB] = device_cat[2 * sNid[tid - KNB] + 1];
    } else if (tid < 160) {
        int l = tid - 128;
        int h = l >> 3, sub = l & 7;
        float s = 0.f;
        for (int f = sub; f < FEAT; f += 8)
            s += sComb[f] * g_vch[h * FPAD + f];
        s += __shfl_down_sync(0xffffffffu, s, 4);
        s += __shfl_down_sync(0xffffffffu, s, 2);
        s += __shfl_down_sync(0xffffffffu, s, 1);
        if (sub == 0) sEbase[h] = s + g_ech[h];
    }
    __syncthreads();

    // ---- Gather: 64 neighbor feature rows, warp per row ----
    {
        const int warp = tid >> 5;
        for (int k = warp; k < KNB; k += 8) {
            int nid = sNid[k], n0 = sCat0[k], n1 = sCat1[k];
            float* dst = sFeat + k * FSTR;
            #pragma unroll
            for (int f = lane; f < FPAD; f += 32) {
                float v;
                if (f < CONT)                 v = device_cont[nid * CONT + f];
                else if (f < CONT + EMB)      v = de0[n0 * EMB + (f - CONT)];
                else if (f < FEAT)            v = de1[n1 * EMB + (f - CONT - EMB)];
                else                          v = 0.f;
                dst[f] = v;
            }
        }
    }
    __syncthreads();

    // ---- S1: partial e-dots; thread (c,k) covers 24 feats for ALL 4 heads ----
    {
        const int k = tid & 63, c = tid >> 6;
        const float4* fp = reinterpret_cast<const float4*>(sFeat + k * FSTR + c * 24);
        const float4* w0 = reinterpret_cast<const float4*>(sWd2 + 0 * FPAD + c * 24);
        const float4* w1 = reinterpret_cast<const float4*>(sWd2 + 1 * FPAD + c * 24);
        const float4* w2 = reinterpret_cast<const float4*>(sWd2 + 2 * FPAD + c * 24);
        const float4* w3 = reinterpret_cast<const float4*>(sWd2 + 3 * FPAD + c * 24);
        float a0 = 0.f, a1 = 0.f, a2 = 0.f, a3 = 0.f;
        #pragma unroll
        for (int ff = 0; ff < 6; ff++) {
            float4 a = fp[ff];
            float4 v0 = w0[ff], v1 = w1[ff], v2 = w2[ff], v3 = w3[ff];
            a0 += a.x * v0.x + a.y * v0.y + a.z * v0.z + a.w * v0.w;
            a1 += a.x * v1.x + a.y * v1.y + a.z * v1.z + a.w * v1.w;
            a2 += a.x * v2.x + a.y * v2.y + a.z * v2.z + a.w * v2.w;
            a3 += a.x * v3.x + a.y * v3.y + a.z * v3.z + a.w * v3.w;
        }
        sEp[c * 256 +   0 + k] = a0;
        sEp[c * 256 +  64 + k] = a1;
        sEp[c * 256 + 128 + k] = a2;
        sEp[c * 256 + 192 + k] = a3;
    }
    __syncthreads();

    // ---- Softmax (combines S1 partials, leaky-relu inline) ----
    if (tid < 128) {
        int h = tid >> 5;
        float eb = sEbase[h];
        float r0 = sEp[h * 64 + lane]       + sEp[256 + h * 64 + lane]
                 + sEp[512 + h * 64 + lane] + sEp[768 + h * 64 + lane] + eb;
        float r1 = sEp[h * 64 + lane + 32]       + sEp[256 + h * 64 + lane + 32]
                 + sEp[512 + h * 64 + lane + 32] + sEp[768 + h * 64 + lane + 32] + eb;
        float v0 = (r0 >= 0.f) ? r0 : 0.2f * r0;
        float v1 = (r1 >= 0.f) ? r1 : 0.2f * r1;
        float m = fmaxf(v0, v1);
        #pragma unroll
        for (int off = 16; off; off >>= 1) m = fmaxf(m, __shfl_xor_sync(0xffffffffu, m, off));
        float e0 = __expf(v0 - m), e1 = __expf(v1 - m);
        float s = e0 + e1;
        #pragma unroll
        for (int off = 16; off; off >>= 1) s += __shfl_xor_sync(0xffffffffu, s, off);
        float inv = __frcp_rn(s);
        sE[h * KNB + lane]      = e0 * inv;
        sE[h * KNB + lane + 32] = e1 * inv;
    }
    __syncthreads();

    // ---- S2: pooled-feature partials (thread = (f, k-half), all 4 heads)
    //      || threads 192-255: comb-part of fusion GEMV ----
    if (tid < 192) {
        const int half = tid / 96;
        const int f = tid - half * 96;
        const int kb = half * 32;
        const float* fp = sFeat + kb * FSTR + f;
        const float* e0 = sE + kb;
        float a0 = 0.f, a1 = 0.f, a2 = 0.f, a3 = 0.f;
        #pragma unroll 4
        for (int k = 0; k < 32; k++) {
            float v = fp[k * FSTR];
            a0 += e0[k]       * v;
            a1 += e0[64 + k]  * v;
            a2 += e0[128 + k] * v;
            a3 += e0[192 + k] * v;
        }
        sMp[half * 384 +   0 + f] = a0;
        sMp[half * 384 +  96 + f] = a1;
        sMp[half * 384 + 192 + f] = a2;
        sMp[half * 384 + 288 + f] = a3;
    } else {
        int j = tid - 192;
        float s = 0.f;
        #pragma unroll 2
        for (int r = 0; r < FEAT; r++)
            s += sComb[r] * g_Wfus[r * 64 + j];
        sPA[j] = s;
    }
    __syncthreads();

    // ---- S3: head projection (combines S2 partials) || dev-part of fusion ----
    if (tid < HO) {
        int h = tid >> 4;
        float s = bd[tid];
        const float* m0 = sMp + h * 96;
        const float* m1 = sMp + 384 + h * 96;
        #pragma unroll 2
        for (int f = 0; f < FEAT; f++)
            s += (m0[f] + m1[f]) * g_Wdp[f * HO + tid];
        sHO[tid] = (s > 0.f) ? s : (__expf(s) - 1.f);
    } else if (tid < 128) {
        int j = tid - 64;
        float s = 0.f;
        #pragma unroll 2
        for (int r = FEAT; r < FEAT + 47; r++)
            s += sDev[r - FEAT] * g_Wfus[r * 64 + j];
        sPB0[j] = s;
    } else if (tid < 192) {
        int j = tid - 128;
        float s = 0.f;
        #pragma unroll 2
        for (int r = FEAT + 47; r < 2 * FEAT; r++)
            s += sDev[r - FEAT] * g_Wfus[r * 64 + j];
        sPB1[j] = s;
    }
    __syncthreads();

    // ---- S4: x2 = relu(b2f + partials + head_out @ W12) ----
    if (tid < 64) {
        float s = g_b2f[tid] + sPA[tid] + sPB0[tid] + sPB1[tid];
        #pragma unroll 4
        for (int i = 0; i < HO; i++)
            s += sHO[i] * g_Wfus[(2 * FEAT + i) * 64 + tid];
        sX2[tid] = fmaxf(s, 0.f);
    }
    __syncthreads();

    // ---- S5: x3 = relu(x2 @ W3 + b3) as 4 partial chunks ----
    if (tid < 128) {
        int j = tid & 31, c = tid >> 5;
        float s = 0.f;
        #pragma unroll
        for (int k = c * 16; k < c * 16 + 16; k++)
            s += sX2[k] * W3[k * 32 + j];
        sP2[c * 32 + j] = s;
    }
    __syncthreads();

    if (tid < 32) {
        float x3 = b3[tid] + sP2[tid] + sP2[32 + tid] + sP2[64 + tid] + sP2[96 + tid];
        x3 = fmaxf(x3, 0.f);
        float v = x3 * W4[tid];
        #pragma unroll
        for (int off = 16; off; off >>= 1) v += __shfl_xor_sync(0xffffffffu, v, off);
        if (tid == 0) out[b] = 1.f / (1.f + __expf(-(v + b4[0])));
    }
}

extern "C" void kernel_launch(void* const* d_in, const int* in_sizes, int n_in,
                              void* d_out, int out_size)
{
    (void)in_sizes; (void)n_in; (void)out_size;

    prep_kernel<<<1, NTHREADS>>>(
        (const float*)d_in[11],  // Wc
        (const float*)d_in[12],  // bc
        (const float*)d_in[13],  // Wd
        (const float*)d_in[14],  // bd
        (const float*)d_in[15],  // aW
        (const float*)d_in[16],  // ab
        (const float*)d_in[17],  // W1
        (const float*)d_in[18],  // b1
        (const float*)d_in[19],  // W2
        (const float*)d_in[20]); // b2

    gat_kernel<<<N_B, NTHREADS>>>(
        (const float*)d_in[0],   // combin_cont
        (const int*)  d_in[1],   // combin_cat
        (const float*)d_in[2],   // device_cont
        (const int*)  d_in[3],   // device_cat
        (const int*)  d_in[4],   // combin_idx
        (const int*)  d_in[5],   // device_idx
        (const int*)  d_in[6],   // neighbor_idx
        (const float*)d_in[7],   // ce0
        (const float*)d_in[8],   // ce1
        (const float*)d_in[9],   // de0
        (const float*)d_in[10],  // de1
        (const float*)d_in[14],  // bd
        (const float*)d_in[21],  // W3
        (const float*)d_in[22],  // b3
        (const float*)d_in[23],  // W4
        (const float*)d_in[24],  // b4
        (float*)d_out);
}

// round 8
// speedup vs baseline: 1.2313x; 1.2313x over previous
#include <cuda_runtime.h>
#include <math.h>

#define N_B      8192
#define CONT     62
#define EMB      16
#define FEAT     94
#define FPAD     96
#define KNB      64
#define NH       4
#define NOUT     16
#define HO       64
#define NTHREADS 256
#define FSTR     100   // sFeat row stride in floats

// ---------------- folded-weight scratch (written by prep_kernel each launch) ----
__device__ float g_wd2[NH * FPAD];     // Wd[h] @ a2[h], f-padded with zeros
__device__ float g_vch[NH * FPAD];     // Wc[h] @ a1[h], f-padded with zeros
__device__ float g_ech[NH];            // bc·a1 + ab + bd·a2
__device__ float g_Wdp[FPAD * HO];     // Wd as [f][h*16+o], zero rows f>=94
__device__ float g_Wfus[(2 * FEAT + HO) * 64];  // 252x64: [W2a; W2b; W1@W2c]
__device__ float g_b2f[64];            // b2 + b1@W2c

__global__ __launch_bounds__(NTHREADS) void prep_kernel(
    const float* __restrict__ Wc, const float* __restrict__ bc,
    const float* __restrict__ Wd, const float* __restrict__ bd,
    const float* __restrict__ aW, const float* __restrict__ ab,
    const float* __restrict__ W1, const float* __restrict__ b1,
    const float* __restrict__ W2, const float* __restrict__ b2)
{
    const int tid = threadIdx.x;

    for (int idx = tid; idx < NH * FPAD; idx += NTHREADS) {
        int h = idx / FPAD, f = idx % FPAD;
        float s2 = 0.f, s1 = 0.f;
        if (f < FEAT) {
            #pragma unroll
            for (int o = 0; o < NOUT; o++) {
                s2 += Wd[(h * FEAT + f) * NOUT + o] * aW[h * 2 * NOUT + NOUT + o];
                s1 += Wc[(h * FEAT + f) * NOUT + o] * aW[h * 2 * NOUT + o];
            }
        }
        g_wd2[idx] = s2;
        g_vch[idx] = s1;
    }
    if (tid < NH) {
        float s = ab[tid];
        #pragma unroll
        for (int o = 0; o < NOUT; o++) {
            s += bc[tid * NOUT + o] * aW[tid * 2 * NOUT + o];
            s += bd[tid * NOUT + o] * aW[tid * 2 * NOUT + NOUT + o];
        }
        g_ech[tid] = s;
    }
    for (int idx = tid; idx < FPAD * HO; idx += NTHREADS) {
        int f = idx >> 6, ho = idx & 63;
        g_Wdp[idx] = (f < FEAT) ? Wd[((ho >> 4) * FEAT + f) * NOUT + (ho & 15)] : 0.f;
    }
    for (int idx = tid; idx < (2 * FEAT + HO) * 64; idx += NTHREADS) {
        int r = idx >> 6, j = idx & 63;
        float v;
        if (r < 2 * FEAT) {
            v = W2[r * 64 + j];
        } else {
            int i = r - 2 * FEAT;
            float s = 0.f;
            #pragma unroll
            for (int t = 0; t < NOUT; t++)
                s += W1[i * NOUT + t] * W2[(2 * FEAT + t) * 64 + j];
            v = s;
        }
        g_Wfus[idx] = v;
    }
    if (tid < 64) {
        float s = b2[tid];
        #pragma unroll
        for (int t = 0; t < NOUT; t++)
            s += b1[t] * W2[(2 * FEAT + t) * 64 + tid];
        g_b2f[tid] = s;
    }
}

// ---------------- main fused kernel: one CTA per batch element -------------------
__global__ __launch_bounds__(NTHREADS) void gat_kernel(
    const float* __restrict__ combin_cont,
    const int*   __restrict__ combin_cat,
    const float* __restrict__ device_cont,
    const int*   __restrict__ device_cat,
    const int*   __restrict__ combin_idx,
    const int*   __restrict__ device_idx,
    const int*   __restrict__ neighbor_idx,
    const float* __restrict__ ce0,
    const float* __restrict__ ce1,
    const float* __restrict__ de0,
    const float* __restrict__ de1,
    const float* __restrict__ bd,
    const float* __restrict__ W3,
    const float* __restrict__ b3,
    const float* __restrict__ W4,
    const float* __restrict__ b4,
    float* __restrict__ out)
{
    __shared__ __align__(16) float sFeat[KNB * FSTR];   // 25600B
    __shared__ __align__(16) float sWd2[NH * FPAD];     // [h][f]
    __shared__ __align__(16) float sM[NH * FPAD];       // pooled features [h][96]
    __shared__ float sE[NH * KNB];                      // attn [h][k]
    __shared__ float sEbase[NH];
    __shared__ float sComb[FPAD];
    __shared__ float sDev[FPAD];
    __shared__ float sHO[HO];
    __shared__ float sX2[64];
    __shared__ float sPA[64];
    __shared__ float sPB[64];
    __shared__ float sP2[4 * 32];
    __shared__ int   sNid[KNB];
    __shared__ int   sCat0[KNB];
    __shared__ int   sCat1[KNB];

    const int b    = blockIdx.x;
    const int tid  = threadIdx.x;
    const int lane = tid & 31;

    // ---- Prologue A: independent loads ----
    if (tid < 96) {
        reinterpret_cast<float4*>(sWd2)[tid] = reinterpret_cast<const float4*>(g_wd2)[tid];
    }
    if (tid < KNB) {
        sNid[tid] = neighbor_idx[b * KNB + tid];
    } else if (tid >= 96 && tid < 96 + FEAT) {
        int f = tid - 96;
        int ci = combin_idx[b];
        float v;
        if (f < CONT)            v = combin_cont[ci * CONT + f];
        else if (f < CONT + EMB) v = ce0[combin_cat[2 * ci]     * EMB + (f - CONT)];
        else                     v = ce1[combin_cat[2 * ci + 1] * EMB + (f - CONT - EMB)];
        sComb[f] = v;
    } else if (tid >= 192 && tid < 192 + 62) {
        int f = tid - 192;
        int di = device_idx[b];
        sDev[f] = device_cont[di * CONT + f];
    } else if (tid >= 64 && tid < 96) {
        int f = tid - 64 + CONT;   // f in [62,94)
        int di = device_idx[b];
        float v;
        if (f < CONT + EMB) v = de0[device_cat[2 * di]     * EMB + (f - CONT)];
        else                v = de1[device_cat[2 * di + 1] * EMB + (f - CONT - EMB)];
        sDev[f] = v;
    }
    __syncthreads();

    // ---- Prologue B: neighbor cat ids + e_base ----
    if (tid < KNB) {
        sCat0[tid] = device_cat[2 * sNid[tid]];
    } else if (tid < 2 * KNB) {
        sCat1[tid - KNB] = device_cat[2 * sNid[tid - KNB] + 1];
    } else if (tid < 160) {
        int l = tid - 128;
        int h = l >> 3, sub = l & 7;
        float s = 0.f;
        for (int f = sub; f < FEAT; f += 8)
            s += sComb[f] * g_vch[h * FPAD + f];
        s += __shfl_down_sync(0xffffffffu, s, 4);
        s += __shfl_down_sync(0xffffffffu, s, 2);
        s += __shfl_down_sync(0xffffffffu, s, 1);
        if (sub == 0) sEbase[h] = s + g_ech[h];
    }
    __syncthreads();

    // ---- Gather: 64 neighbor feature rows, warp per row, float2 vectorized ----
    {
        const int warp = tid >> 5;
        for (int k = warp; k < KNB; k += 8) {
            const int nid = sNid[k], n0 = sCat0[k], n1 = sCat1[k];
            float* dst = sFeat + k * FSTR;
            if (lane < 31) {
                float2 v = *reinterpret_cast<const float2*>(device_cont + (size_t)nid * CONT + 2 * lane);
                *reinterpret_cast<float2*>(dst + 2 * lane) = v;
            } else {
                *reinterpret_cast<float2*>(dst + 94) = make_float2(0.f, 0.f);
            }
            if (lane < 8) {
                float2 v = *reinterpret_cast<const float2*>(de0 + (size_t)n0 * EMB + 2 * lane);
                *reinterpret_cast<float2*>(dst + 62 + 2 * lane) = v;
            } else if (lane < 16) {
                float2 v = *reinterpret_cast<const float2*>(de1 + (size_t)n1 * EMB + 2 * (lane - 8));
                *reinterpret_cast<float2*>(dst + 78 + 2 * (lane - 8)) = v;
            }
        }
    }
    __syncthreads();

    // ---- S1: e[h][k] = feat_k . wd2[h] + e_base[h], leaky-relu ----
    {
        int k = tid & 63, h = tid >> 6;
        const float4* fp = reinterpret_cast<const float4*>(sFeat) + k * (FSTR / 4);
        const float4* wp = reinterpret_cast<const float4*>(sWd2) + h * (FPAD / 4);
        float ax = 0.f, ay = 0.f, az = 0.f, aw = 0.f;
        #pragma unroll
        for (int ff = 0; ff < FPAD / 4; ff++) {
            float4 a = fp[ff];
            float4 w = wp[ff];
            ax += a.x * w.x; ay += a.y * w.y; az += a.z * w.z; aw += a.w * w.w;
        }
        float e = (ax + ay) + (az + aw) + sEbase[h];
        sE[h * KNB + k] = (e >= 0.f) ? e : 0.2f * e;
    }
    __syncthreads();

    // ---- softmax over k per head (warp h) ----
    if (tid < 128) {
        int h = tid >> 5;
        float v0 = sE[h * KNB + lane];
        float v1 = sE[h * KNB + lane + 32];
        float m = fmaxf(v0, v1);
        #pragma unroll
        for (int off = 16; off; off >>= 1) m = fmaxf(m, __shfl_xor_sync(0xffffffffu, m, off));
        float e0 = __expf(v0 - m), e1 = __expf(v1 - m);
        float s = e0 + e1;
        #pragma unroll
        for (int off = 16; off; off >>= 1) s += __shfl_xor_sync(0xffffffffu, s, off);
        float inv = __frcp_rn(s);
        sE[h * KNB + lane]      = e0 * inv;
        sE[h * KNB + lane + 32] = e1 * inv;
    }
    __syncthreads();

    // ---- S2: pooled features (thread f, ALL 4 heads, sFeat column read once)
    //      || threads 96-223: comb/dev fusion GEMV partials ----
    if (tid < 96) {
        const int f = tid;
        const float* fp = sFeat + f;
        float a0 = 0.f, a1 = 0.f, a2 = 0.f, a3 = 0.f;
        #pragma unroll 4
        for (int k = 0; k < KNB; k++) {
            float v = fp[k * FSTR];
            a0 += sE[k]       * v;
            a1 += sE[64 + k]  * v;
            a2 += sE[128 + k] * v;
            a3 += sE[192 + k] * v;
        }
        sM[f]       = a0;
        sM[96 + f]  = a1;
        sM[192 + f] = a2;
        sM[288 + f] = a3;
    } else if (tid < 160) {
        int j = tid - 96;
        float s = 0.f;
        #pragma unroll 2
        for (int r = 0; r < FEAT; r++)
            s += sComb[r] * g_Wfus[r * 64 + j];
        sPA[j] = s;
    } else if (tid < 224) {
        int j = tid - 160;
        float s = 0.f;
        #pragma unroll 2
        for (int r = 0; r < FEAT; r++)
            s += sDev[r] * g_Wfus[(FEAT + r) * 64 + j];
        sPB[j] = s;
    }
    __syncthreads();

    // ---- S3: head projection head_out = elu(m[h] @ Wd[h] + bd) ----
    if (tid < HO) {
        int h = tid >> 4;
        float s = bd[tid];
        const float* mp = sM + h * 96;
        #pragma unroll 2
        for (int f = 0; f < FEAT; f++)
            s += mp[f] * g_Wdp[f * HO + tid];
        sHO[tid] = (s > 0.f) ? s : (__expf(s) - 1.f);
    }
    __syncthreads();

    // ---- S4: x2 = relu(b2f + partials + head_out @ W12) ----
    if (tid < 64) {
        float s = g_b2f[tid] + sPA[tid] + sPB[tid];
        #pragma unroll 4
        for (int i = 0; i < HO; i++)
            s += sHO[i] * g_Wfus[(2 * FEAT + i) * 64 + tid];
        sX2[tid] = fmaxf(s, 0.f);
    }
    __syncthreads();

    // ---- S5: x3 = relu(x2 @ W3 + b3) as 4 partial chunks ----
    if (tid < 128) {
        int j = tid & 31, c = tid >> 5;
        float s = 0.f;
        #pragma unroll
        for (int k = c * 16; k < c * 16 + 16; k++)
            s += sX2[k] * W3[k * 32 + j];
        sP2[c * 32 + j] = s;
    }
    __syncthreads();

    if (tid < 32) {
        float x3 = b3[tid] + sP2[tid] + sP2[32 + tid] + sP2[64 + tid] + sP2[96 + tid];
        x3 = fmaxf(x3, 0.f);
        float v = x3 * W4[tid];
        #pragma unroll
        for (int off = 16; off; off >>= 1) v += __shfl_xor_sync(0xffffffffu, v, off);
        if (tid == 0) out[b] = 1.f / (1.f + __expf(-(v + b4[0])));
    }
}

extern "C" void kernel_launch(void* const* d_in, const int* in_sizes, int n_in,
                              void* d_out, int out_size)
{
    (void)in_sizes; (void)n_in; (void)out_size;

    prep_kernel<<<1, NTHREADS>>>(
        (const float*)d_in[11],  // Wc
        (const float*)d_in[12],  // bc
        (const float*)d_in[13],  // Wd
        (const float*)d_in[14],  // bd
        (const float*)d_in[15],  // aW
        (const float*)d_in[16],  // ab
        (const float*)d_in[17],  // W1
        (const float*)d_in[18],  // b1
        (const float*)d_in[19],  // W2
        (const float*)d_in[20]); // b2

    gat_kernel<<<N_B, NTHREADS>>>(
        (const float*)d_in[0],   // combin_cont
        (const int*)  d_in[1],   // combin_cat
        (const float*)d_in[2],   // device_cont
        (const int*)  d_in[3],   // device_cat
        (const int*)  d_in[4],   // combin_idx
        (const int*)  d_in[5],   // device_idx
        (const int*)  d_in[6],   // neighbor_idx
        (const float*)d_in[7],   // ce0
        (const float*)d_in[8],   // ce1
        (const float*)d_in[9],   // de0
        (const float*)d_in[10],  // de1
        (const float*)d_in[14],  // bd
        (const float*)d_in[21],  // W3
        (const float*)d_in[22],  // b3
        (const float*)d_in[23],  // W4
        (const float*)d_in[24],  // b4
        (float*)d_out);
}

// round 9
// speedup vs baseline: 1.5032x; 1.2208x over previous
#include <cuda_runtime.h>
#include <math.h>

#define N_B      8192
#define CONT     62
#define EMB      16
#define FEAT     94
#define FPAD     96
#define KNB      64
#define NH       4
#define NOUT     16
#define HO       64
#define NTHREADS 256
#define FSTR     100   // sFeat row stride in floats

// ---------------- folded-weight scratch (written by prep_kernel each launch) ----
__device__ float g_wd2[NH * FPAD];     // Wd[h] @ a2[h], f-padded with zeros
__device__ float g_vch[NH * FPAD];     // Wc[h] @ a1[h], f-padded with zeros
__device__ float g_ech[NH];            // bc·a1 + ab + bd·a2
__device__ float g_Wdp[FPAD * HO];     // Wd as [f][h*16+o], zero rows f>=94
__device__ float g_Wfus[(2 * FEAT + HO) * 64];  // 252x64: [W2a; W2b; W1@W2c]
__device__ float g_b2f[64];            // b2 + b1@W2c

__global__ __launch_bounds__(NTHREADS) void prep_kernel(
    const float* __restrict__ Wc, const float* __restrict__ bc,
    const float* __restrict__ Wd, const float* __restrict__ bd,
    const float* __restrict__ aW, const float* __restrict__ ab,
    const float* __restrict__ W1, const float* __restrict__ b1,
    const float* __restrict__ W2, const float* __restrict__ b2)
{
    const int tid = threadIdx.x;

    for (int idx = tid; idx < NH * FPAD; idx += NTHREADS) {
        int h = idx / FPAD, f = idx % FPAD;
        float s2 = 0.f, s1 = 0.f;
        if (f < FEAT) {
            #pragma unroll
            for (int o = 0; o < NOUT; o++) {
                s2 += Wd[(h * FEAT + f) * NOUT + o] * aW[h * 2 * NOUT + NOUT + o];
                s1 += Wc[(h * FEAT + f) * NOUT + o] * aW[h * 2 * NOUT + o];
            }
        }
        g_wd2[idx] = s2;
        g_vch[idx] = s1;
    }
    if (tid < NH) {
        float s = ab[tid];
        #pragma unroll
        for (int o = 0; o < NOUT; o++) {
            s += bc[tid * NOUT + o] * aW[tid * 2 * NOUT + o];
            s += bd[tid * NOUT + o] * aW[tid * 2 * NOUT + NOUT + o];
        }
        g_ech[tid] = s;
    }
    for (int idx = tid; idx < FPAD * HO; idx += NTHREADS) {
        int f = idx >> 6, ho = idx & 63;
        g_Wdp[idx] = (f < FEAT) ? Wd[((ho >> 4) * FEAT + f) * NOUT + (ho & 15)] : 0.f;
    }
    for (int idx = tid; idx < (2 * FEAT + HO) * 64; idx += NTHREADS) {
        int r = idx >> 6, j = idx & 63;
        float v;
        if (r < 2 * FEAT) {
            v = W2[r * 64 + j];
        } else {
            int i = r - 2 * FEAT;
            float s = 0.f;
            #pragma unroll
            for (int t = 0; t < NOUT; t++)
                s += W1[i * NOUT + t] * W2[(2 * FEAT + t) * 64 + j];
            v = s;
        }
        g_Wfus[idx] = v;
    }
    if (tid < 64) {
        float s = b2[tid];
        #pragma unroll
        for (int t = 0; t < NOUT; t++)
            s += b1[t] * W2[(2 * FEAT + t) * 64 + tid];
        g_b2f[tid] = s;
    }
}

// ---------------- main fused kernel: one CTA per batch element -------------------
__global__ __launch_bounds__(NTHREADS) void gat_kernel(
    const float* __restrict__ combin_cont,
    const int*   __restrict__ combin_cat,
    const float* __restrict__ device_cont,
    const int*   __restrict__ device_cat,
    const int*   __restrict__ combin_idx,
    const int*   __restrict__ device_idx,
    const int*   __restrict__ neighbor_idx,
    const float* __restrict__ ce0,
    const float* __restrict__ ce1,
    const float* __restrict__ de0,
    const float* __restrict__ de1,
    const float* __restrict__ bd,
    const float* __restrict__ W3,
    const float* __restrict__ b3,
    const float* __restrict__ W4,
    const float* __restrict__ b4,
    float* __restrict__ out)
{
    __shared__ __align__(16) float sFeat[KNB * FSTR];   // 25600B
    __shared__ __align__(16) float sWd2[NH * FPAD];     // [h][f]
    __shared__ __align__(16) float sM[NH * FPAD];       // pooled features [h][96]
    __shared__ float sE[NH * KNB];                      // attn [h][k]
    __shared__ float sEbase[NH];
    __shared__ float sComb[FPAD];
    __shared__ float sDev[FPAD];
    __shared__ float sHO[HO];
    __shared__ float sX2[64];
    __shared__ float sPA[64];
    __shared__ float sPB0[64];
    __shared__ float sPB1[64];
    __shared__ float sP2[4 * 32];
    __shared__ int   sNid[KNB];
    __shared__ int   sCat0[KNB];
    __shared__ int   sCat1[KNB];

    const int b    = blockIdx.x;
    const int tid  = threadIdx.x;
    const int lane = tid & 31;

    // ---- Prologue A: independent loads ----
    if (tid < 96) {
        reinterpret_cast<float4*>(sWd2)[tid] = reinterpret_cast<const float4*>(g_wd2)[tid];
    }
    if (tid < KNB) {
        sNid[tid] = neighbor_idx[b * KNB + tid];
    } else if (tid >= 96 && tid < 96 + FEAT) {
        int f = tid - 96;
        int ci = combin_idx[b];
        float v;
        if (f < CONT)            v = combin_cont[ci * CONT + f];
        else if (f < CONT + EMB) v = ce0[combin_cat[2 * ci]     * EMB + (f - CONT)];
        else                     v = ce1[combin_cat[2 * ci + 1] * EMB + (f - CONT - EMB)];
        sComb[f] = v;
    } else if (tid >= 192 && tid < 192 + 62) {
        int f = tid - 192;
        int di = device_idx[b];
        sDev[f] = device_cont[di * CONT + f];
    } else if (tid >= 64 && tid < 96) {
        int f = tid - 64 + CONT;   // f in [62,94)
        int di = device_idx[b];
        float v;
        if (f < CONT + EMB) v = de0[device_cat[2 * di]     * EMB + (f - CONT)];
        else                v = de1[device_cat[2 * di + 1] * EMB + (f - CONT - EMB)];
        sDev[f] = v;
    }
    __syncthreads();

    // ---- Prologue B: neighbor cat ids + e_base ----
    if (tid < KNB) {
        sCat0[tid] = device_cat[2 * sNid[tid]];
    } else if (tid < 2 * KNB) {
        sCat1[tid - KNB] = device_cat[2 * sNid[tid - KNB] + 1];
    } else if (tid < 160) {
        int l = tid - 128;
        int h = l >> 3, sub = l & 7;
        float s = 0.f;
        for (int f = sub; f < FEAT; f += 8)
            s += sComb[f] * g_vch[h * FPAD + f];
        s += __shfl_down_sync(0xffffffffu, s, 4);
        s += __shfl_down_sync(0xffffffffu, s, 2);
        s += __shfl_down_sync(0xffffffffu, s, 1);
        if (sub == 0) sEbase[h] = s + g_ech[h];
    }
    __syncthreads();

    // ---- Gather: 64 neighbor feature rows, warp per row, float2 vectorized ----
    {
        const int warp = tid >> 5;
        #pragma unroll
        for (int k = warp; k < KNB; k += 8) {
            const int nid = sNid[k], n0 = sCat0[k], n1 = sCat1[k];
            float* dst = sFeat + k * FSTR;
            if (lane < 31) {
                float2 v = *reinterpret_cast<const float2*>(device_cont + (size_t)nid * CONT + 2 * lane);
                *reinterpret_cast<float2*>(dst + 2 * lane) = v;
            } else {
                *reinterpret_cast<float2*>(dst + 94) = make_float2(0.f, 0.f);
            }
            if (lane < 8) {
                float2 v = *reinterpret_cast<const float2*>(de0 + (size_t)n0 * EMB + 2 * lane);
                *reinterpret_cast<float2*>(dst + 62 + 2 * lane) = v;
            } else if (lane < 16) {
                float2 v = *reinterpret_cast<const float2*>(de1 + (size_t)n1 * EMB + 2 * (lane - 8));
                *reinterpret_cast<float2*>(dst + 78 + 2 * (lane - 8)) = v;
            }
        }
    }
    __syncthreads();

    // ---- S1: e[h][k] = feat_k . wd2[h] + e_base[h], leaky-relu ----
    {
        int k = tid & 63, h = tid >> 6;
        const float4* fp = reinterpret_cast<const float4*>(sFeat) + k * (FSTR / 4);
        const float4* wp = reinterpret_cast<const float4*>(sWd2) + h * (FPAD / 4);
        float ax = 0.f, ay = 0.f, az = 0.f, aw = 0.f;
        #pragma unroll
        for (int ff = 0; ff < FPAD / 4; ff++) {
            float4 a = fp[ff];
            float4 w = wp[ff];
            ax += a.x * w.x; ay += a.y * w.y; az += a.z * w.z; aw += a.w * w.w;
        }
        float e = (ax + ay) + (az + aw) + sEbase[h];
        sE[h * KNB + k] = (e >= 0.f) ? e : 0.2f * e;
    }
    __syncthreads();

    // ---- softmax over k per head (warp h) ----
    if (tid < 128) {
        int h = tid >> 5;
        float v0 = sE[h * KNB + lane];
        float v1 = sE[h * KNB + lane + 32];
        float m = fmaxf(v0, v1);
        #pragma unroll
        for (int off = 16; off; off >>= 1) m = fmaxf(m, __shfl_xor_sync(0xffffffffu, m, off));
        float e0 = __expf(v0 - m), e1 = __expf(v1 - m);
        float s = e0 + e1;
        #pragma unroll
        for (int off = 16; off; off >>= 1) s += __shfl_xor_sync(0xffffffffu, s, off);
        float inv = __frcp_rn(s);
        sE[h * KNB + lane]      = e0 * inv;
        sE[h * KNB + lane + 32] = e1 * inv;
    }
    __syncthreads();

    // ---- S2: pooled features m[h][f] = sum_k attn[h][k] * feat[k][f]
    //      (two passes of 256 threads over 384 (h,f) pairs — full parallelism) ----
    #pragma unroll
    for (int pass = 0; pass < 2; pass++) {
        int idx = pass * NTHREADS + tid;
        if (idx < NH * FPAD) {
            int h = idx / FPAD, f = idx % FPAD;
            float s = 0.f;
            const float* ep = sE + h * KNB;
            const float* fp = sFeat + f;
            #pragma unroll 8
            for (int k = 0; k < KNB; k++)
                s += ep[k] * fp[k * FSTR];
            sM[idx] = s;
        }
    }
    __syncthreads();

    // ---- S3 (threads 0-63): head_out = elu(m[h] @ Wd[h] + bd) || fusion partials ----
    if (tid < HO) {
        int h = tid >> 4;
        float s = bd[tid];
        const float* mp = sM + h * FPAD;
        #pragma unroll 2
        for (int f = 0; f < FEAT; f++)
            s += mp[f] * g_Wdp[f * HO + tid];
        sHO[tid] = (s > 0.f) ? s : (__expf(s) - 1.f);
    } else {
        // threads 64-255: comb/dev part of fusion layer (3 chunks of ~63 rows)
        int t = tid - 64;
        int c = t >> 6, j = t & 63;
        int r0 = c * 63;
        int r1 = (c == 2) ? 2 * FEAT : r0 + 63;
        float s = 0.f;
        for (int r = r0; r < r1; r++) {
            float fv = (r < FEAT) ? sComb[r] : sDev[r - FEAT];
            s += fv * g_Wfus[r * 64 + j];
        }
        if (c == 0) sPA[j]  = s;
        else if (c == 1) sPB0[j] = s;
        else sPB1[j] = s;
    }
    __syncthreads();

    // ---- S4: x2 = relu(b2f + partials + head_out @ W12) ----
    if (tid < 64) {
        float s = g_b2f[tid] + sPA[tid] + sPB0[tid] + sPB1[tid];
        #pragma unroll 4
        for (int i = 0; i < HO; i++)
            s += sHO[i] * g_Wfus[(2 * FEAT + i) * 64 + tid];
        sX2[tid] = fmaxf(s, 0.f);
    }
    __syncthreads();

    // ---- S5: x3 = relu(x2 @ W3 + b3) as 4 partial chunks ----
    if (tid < 128) {
        int j = tid & 31, c = tid >> 5;
        float s = 0.f;
        #pragma unroll
        for (int k = c * 16; k < c * 16 + 16; k++)
            s += sX2[k] * W3[k * 32 + j];
        sP2[c * 32 + j] = s;
    }
    __syncthreads();

    if (tid < 32) {
        float x3 = b3[tid] + sP2[tid] + sP2[32 + tid] + sP2[64 + tid] + sP2[96 + tid];
        x3 = fmaxf(x3, 0.f);
        float v = x3 * W4[tid];
        #pragma unroll
        for (int off = 16; off; off >>= 1) v += __shfl_xor_sync(0xffffffffu, v, off);
        if (tid == 0) out[b] = 1.f / (1.f + __expf(-(v + b4[0])));
    }
}

extern "C" void kernel_launch(void* const* d_in, const int* in_sizes, int n_in,
                              void* d_out, int out_size)
{
    (void)in_sizes; (void)n_in; (void)out_size;

    prep_kernel<<<1, NTHREADS>>>(
        (const float*)d_in[11],  // Wc
        (const float*)d_in[12],  // bc
        (const float*)d_in[13],  // Wd
        (const float*)d_in[14],  // bd
        (const float*)d_in[15],  // aW
        (const float*)d_in[16],  // ab
        (const float*)d_in[17],  // W1
        (const float*)d_in[18],  // b1
        (const float*)d_in[19],  // W2
        (const float*)d_in[20]); // b2

    gat_kernel<<<N_B, NTHREADS>>>(
        (const float*)d_in[0],   // combin_cont
        (const int*)  d_in[1],   // combin_cat
        (const float*)d_in[2],   // device_cont
        (const int*)  d_in[3],   // device_cat
        (const int*)  d_in[4],   // combin_idx
        (const int*)  d_in[5],   // device_idx
        (const int*)  d_in[6],   // neighbor_idx
        (const float*)d_in[7],   // ce0
        (const float*)d_in[8],   // ce1
        (const float*)d_in[9],   // de0
        (const float*)d_in[10],  // de1
        (const float*)d_in[14],  // bd
        (const float*)d_in[21],  // W3
        (const float*)d_in[22],  // b3
        (const float*)d_in[23],  // W4
        (const float*)d_in[24],  // b4
        (float*)d_out);
}

// round 10
// speedup vs baseline: 1.5324x; 1.0194x over previous
#include <cuda_runtime.h>
#include <math.h>

#define N_B      8192
#define N_DEV    100000
#define CONT     62
#define EMB      16
#define FEAT     94
#define FPAD     96
#define KNB      64
#define NH       4
#define NOUT     16
#define HO       64
#define NTHREADS 256
#define FSTR     100   // sFeat row stride in floats

// ---------------- scratch (written per launch, before gat_kernel) ---------------
__device__ float g_dev_feats[N_DEV * FPAD];  // dense padded device features, 38.4MB
__device__ float g_wd2[NH * FPAD];           // Wd[h] @ a2[h], f-padded with zeros
__device__ float g_vch[NH * FPAD];           // Wc[h] @ a1[h], f-padded with zeros
__device__ float g_ech[NH];                  // bc·a1 + ab + bd·a2
__device__ float g_Wdp[FPAD * HO];           // Wd as [f][h*16+o], zero rows f>=94
__device__ float g_Wfus[(2 * FEAT + HO) * 64];  // 252x64: [W2a; W2b; W1@W2c]
__device__ float g_b2f[64];                  // b2 + b1@W2c

// ---- dense device-feature table: dev_feats[row][f], padded to 96 ----
__global__ void devfeat_kernel(
    const float* __restrict__ device_cont,
    const int*   __restrict__ device_cat,
    const float* __restrict__ de0,
    const float* __restrict__ de1)
{
    const int row = blockIdx.x;
    const int f   = threadIdx.x;   // 0..95
    float v;
    if (f < CONT)            v = device_cont[(size_t)row * CONT + f];
    else if (f < CONT + EMB) v = de0[device_cat[2 * row]     * EMB + (f - CONT)];
    else if (f < FEAT)       v = de1[device_cat[2 * row + 1] * EMB + (f - CONT - EMB)];
    else                     v = 0.f;
    g_dev_feats[(size_t)row * FPAD + f] = v;
}

__global__ __launch_bounds__(NTHREADS) void prep_kernel(
    const float* __restrict__ Wc, const float* __restrict__ bc,
    const float* __restrict__ Wd, const float* __restrict__ bd,
    const float* __restrict__ aW, const float* __restrict__ ab,
    const float* __restrict__ W1, const float* __restrict__ b1,
    const float* __restrict__ W2, const float* __restrict__ b2)
{
    const int tid = threadIdx.x;

    for (int idx = tid; idx < NH * FPAD; idx += NTHREADS) {
        int h = idx / FPAD, f = idx % FPAD;
        float s2 = 0.f, s1 = 0.f;
        if (f < FEAT) {
            #pragma unroll
            for (int o = 0; o < NOUT; o++) {
                s2 += Wd[(h * FEAT + f) * NOUT + o] * aW[h * 2 * NOUT + NOUT + o];
                s1 += Wc[(h * FEAT + f) * NOUT + o] * aW[h * 2 * NOUT + o];
            }
        }
        g_wd2[idx] = s2;
        g_vch[idx] = s1;
    }
    if (tid < NH) {
        float s = ab[tid];
        #pragma unroll
        for (int o = 0; o < NOUT; o++) {
            s += bc[tid * NOUT + o] * aW[tid * 2 * NOUT + o];
            s += bd[tid * NOUT + o] * aW[tid * 2 * NOUT + NOUT + o];
        }
        g_ech[tid] = s;
    }
    for (int idx = tid; idx < FPAD * HO; idx += NTHREADS) {
        int f = idx >> 6, ho = idx & 63;
        g_Wdp[idx] = (f < FEAT) ? Wd[((ho >> 4) * FEAT + f) * NOUT + (ho & 15)] : 0.f;
    }
    for (int idx = tid; idx < (2 * FEAT + HO) * 64; idx += NTHREADS) {
        int r = idx >> 6, j = idx & 63;
        float v;
        if (r < 2 * FEAT) {
            v = W2[r * 64 + j];
        } else {
            int i = r - 2 * FEAT;
            float s = 0.f;
            #pragma unroll
            for (int t = 0; t < NOUT; t++)
                s += W1[i * NOUT + t] * W2[(2 * FEAT + t) * 64 + j];
            v = s;
        }
        g_Wfus[idx] = v;
    }
    if (tid < 64) {
        float s = b2[tid];
        #pragma unroll
        for (int t = 0; t < NOUT; t++)
            s += b1[t] * W2[(2 * FEAT + t) * 64 + tid];
        g_b2f[tid] = s;
    }
}

// ---------------- main fused kernel: one CTA per batch element -------------------
__global__ __launch_bounds__(NTHREADS) void gat_kernel(
    const float* __restrict__ combin_cont,
    const int*   __restrict__ combin_cat,
    const int*   __restrict__ combin_idx,
    const int*   __restrict__ device_idx,
    const int*   __restrict__ neighbor_idx,
    const float* __restrict__ ce0,
    const float* __restrict__ ce1,
    const float* __restrict__ bd,
    const float* __restrict__ W3,
    const float* __restrict__ b3,
    const float* __restrict__ W4,
    const float* __restrict__ b4,
    float* __restrict__ out)
{
    __shared__ __align__(16) float sFeat[KNB * FSTR];   // 25600B
    __shared__ __align__(16) float sWd2[NH * FPAD];     // [h][f]
    __shared__ __align__(16) float sM[NH * FPAD];       // pooled features [h][96]
    __shared__ float sE[NH * KNB];                      // attn [h][k]
    __shared__ float sEbase[NH];
    __shared__ float sComb[FPAD];
    __shared__ float sDev[FPAD];
    __shared__ float sHO[HO];
    __shared__ float sX2[64];
    __shared__ float sPart[3 * 64];
    __shared__ float sP2[4 * 32];
    __shared__ int   sNid[KNB];

    const int b    = blockIdx.x;
    const int tid  = threadIdx.x;
    const int lane = tid & 31;
    const int warp = tid >> 5;

    // ---- Prologue: all independent loads, one phase ----
    if (tid < 96) {
        reinterpret_cast<float4*>(sWd2)[tid] = reinterpret_cast<const float4*>(g_wd2)[tid];
    }
    if (tid < KNB) {
        sNid[tid] = neighbor_idx[b * KNB + tid];
    } else if (tid < 64 + FEAT) {
        int f = tid - 64;
        int ci = combin_idx[b];
        float v;
        if (f < CONT)            v = combin_cont[ci * CONT + f];
        else if (f < CONT + EMB) v = ce0[combin_cat[2 * ci]     * EMB + (f - CONT)];
        else                     v = ce1[combin_cat[2 * ci + 1] * EMB + (f - CONT - EMB)];
        sComb[f] = v;
    } else if (tid >= 160) {
        int f = tid - 160;   // 0..95
        int di = device_idx[b];
        sDev[f] = g_dev_feats[(size_t)di * FPAD + f];
    }
    __syncthreads();

    // ---- Gather (warps 0-6, dense float4 rows) + e_base (warp 7) ----
    if (warp < 7) {
        for (int k = warp; k < KNB; k += 7) {
            const int nid = sNid[k];
            if (lane < 24) {
                float4 v = *reinterpret_cast<const float4*>(g_dev_feats + (size_t)nid * FPAD + 4 * lane);
                *reinterpret_cast<float4*>(sFeat + k * FSTR + 4 * lane) = v;
            }
        }
    } else {
        int h = lane >> 3, sub = lane & 7;
        float s = 0.f;
        for (int f = sub; f < FEAT; f += 8)
            s += sComb[f] * g_vch[h * FPAD + f];
        s += __shfl_down_sync(0xffffffffu, s, 4);
        s += __shfl_down_sync(0xffffffffu, s, 2);
        s += __shfl_down_sync(0xffffffffu, s, 1);
        if (sub == 0) sEbase[h] = s + g_ech[h];
    }
    __syncthreads();

    // ---- S1: e[h][k] = feat_k . wd2[h] + e_base[h], leaky-relu ----
    {
        int k = tid & 63, h = tid >> 6;
        const float4* fp = reinterpret_cast<const float4*>(sFeat) + k * (FSTR / 4);
        const float4* wp = reinterpret_cast<const float4*>(sWd2) + h * (FPAD / 4);
        float ax = 0.f, ay = 0.f, az = 0.f, aw = 0.f;
        #pragma unroll
        for (int ff = 0; ff < FPAD / 4; ff++) {
            float4 a = fp[ff];
            float4 w = wp[ff];
            ax += a.x * w.x; ay += a.y * w.y; az += a.z * w.z; aw += a.w * w.w;
        }
        float e = (ax + ay) + (az + aw) + sEbase[h];
        sE[h * KNB + k] = (e >= 0.f) ? e : 0.2f * e;
    }
    __syncthreads();

    // ---- softmax over k per head (warp h) ----
    if (tid < 128) {
        int h = tid >> 5;
        float v0 = sE[h * KNB + lane];
        float v1 = sE[h * KNB + lane + 32];
        float m = fmaxf(v0, v1);
        #pragma unroll
        for (int off = 16; off; off >>= 1) m = fmaxf(m, __shfl_xor_sync(0xffffffffu, m, off));
        float e0 = __expf(v0 - m), e1 = __expf(v1 - m);
        float s = e0 + e1;
        #pragma unroll
        for (int off = 16; off; off >>= 1) s += __shfl_xor_sync(0xffffffffu, s, off);
        float inv = __frcp_rn(s);
        sE[h * KNB + lane]      = e0 * inv;
        sE[h * KNB + lane + 32] = e1 * inv;
    }
    __syncthreads();

    // ---- S2: pooled features m[h][f] = sum_k attn[h][k] * feat[k][f] ----
    #pragma unroll
    for (int pass = 0; pass < 2; pass++) {
        int idx = pass * NTHREADS + tid;
        if (idx < NH * FPAD) {
            int h = idx / FPAD, f = idx % FPAD;
            float s = 0.f;
            const float* ep = sE + h * KNB;
            const float* fp = sFeat + f;
            #pragma unroll 8
            for (int k = 0; k < KNB; k++)
                s += ep[k] * fp[k * FSTR];
            sM[idx] = s;
        }
    }
    __syncthreads();

    // ---- S3 (threads 0-63): head_out = elu(m[h] @ Wd[h] + bd) || fusion partials ----
    if (tid < HO) {
        int h = tid >> 4;
        float s = bd[tid];
        const float* mp = sM + h * FPAD;
        #pragma unroll 2
        for (int f = 0; f < FEAT; f++)
            s += mp[f] * g_Wdp[f * HO + tid];
        sHO[tid] = (s > 0.f) ? s : (__expf(s) - 1.f);
    } else {
        // threads 64-255: comb/dev part of fusion layer (3 chunks of ~63 rows)
        int t = tid - 64;
        int c = t >> 6, j = t & 63;
        int r0 = c * 63;
        int r1 = (c == 2) ? 2 * FEAT : r0 + 63;
        float s = 0.f;
        for (int r = r0; r < r1; r++) {
            float fv = (r < FEAT) ? sComb[r] : sDev[r - FEAT];
            s += fv * g_Wfus[r * 64 + j];
        }
        sPart[c * 64 + j] = s;
    }
    __syncthreads();

    // ---- S4: x2 = relu(b2f + partials + head_out @ W12) ----
    if (tid < 64) {
        float s = g_b2f[tid] + sPart[tid] + sPart[64 + tid] + sPart[128 + tid];
        #pragma unroll 4
        for (int i = 0; i < HO; i++)
            s += sHO[i] * g_Wfus[(2 * FEAT + i) * 64 + tid];
        sX2[tid] = fmaxf(s, 0.f);
    }
    __syncthreads();

    // ---- S5: x3 = relu(x2 @ W3 + b3) as 4 partial chunks ----
    if (tid < 128) {
        int j = tid & 31, c = tid >> 5;
        float s = 0.f;
        #pragma unroll
        for (int k = c * 16; k < c * 16 + 16; k++)
            s += sX2[k] * W3[k * 32 + j];
        sP2[c * 32 + j] = s;
    }
    __syncthreads();

    if (tid < 32) {
        float x3 = b3[tid] + sP2[tid] + sP2[32 + tid] + sP2[64 + tid] + sP2[96 + tid];
        x3 = fmaxf(x3, 0.f);
        float v = x3 * W4[tid];
        #pragma unroll
        for (int off = 16; off; off >>= 1) v += __shfl_xor_sync(0xffffffffu, v, off);
        if (tid == 0) out[b] = 1.f / (1.f + __expf(-(v + b4[0])));
    }
}

extern "C" void kernel_launch(void* const* d_in, const int* in_sizes, int n_in,
                              void* d_out, int out_size)
{
    (void)in_sizes; (void)n_in; (void)out_size;

    devfeat_kernel<<<N_DEV, FPAD>>>(
        (const float*)d_in[2],   // device_cont
        (const int*)  d_in[3],   // device_cat
        (const float*)d_in[9],   // de0
        (const float*)d_in[10]); // de1

    prep_kernel<<<1, NTHREADS>>>(
        (const float*)d_in[11],  // Wc
        (const float*)d_in[12],  // bc
        (const float*)d_in[13],  // Wd
        (const float*)d_in[14],  // bd
        (const float*)d_in[15],  // aW
        (const float*)d_in[16],  // ab
        (const float*)d_in[17],  // W1
        (const float*)d_in[18],  // b1
        (const float*)d_in[19],  // W2
        (const float*)d_in[20]); // b2

    gat_kernel<<<N_B, NTHREADS>>>(
        (const float*)d_in[0],   // combin_cont
        (const int*)  d_in[1],   // combin_cat
        (const int*)  d_in[4],   // combin_idx
        (const int*)  d_in[5],   // device_idx
        (const int*)  d_in[6],   // neighbor_idx
        (const float*)d_in[7],   // ce0
        (const float*)d_in[8],   // ce1
        (const float*)d_in[14],  // bd
        (const float*)d_in[21],  // W3
        (const float*)d_in[22],  // b3
        (const float*)d_in[23],  // W4
        (const float*)d_in[24],  // b4
        (float*)d_out);
}

// round 11
// speedup vs baseline: 1.8067x; 1.1790x over previous
#include <cuda_runtime.h>
#include <math.h>

#define N_B      8192
#define N_DEV    100000
#define CONT     62
#define EMB      16
#define FEAT     94
#define FPAD     96
#define KNB      64
#define NH       4
#define NOUT     16
#define HO       64
#define NTHREADS 256
#define FSTR     100   // sFeat row stride in floats

// ---------------- scratch (written per launch, before gat_kernel) ---------------
__device__ float g_dev_feats[N_DEV * FPAD];  // dense padded device features, 38.4MB
__device__ float g_wd2[NH * FPAD];           // Wd[h] @ a2[h], f-padded with zeros
__device__ float g_vch[NH * FPAD];           // Wc[h] @ a1[h], f-padded with zeros
__device__ float g_ech[NH];                  // bc·a1 + ab + bd·a2
__device__ float g_Wdp[FPAD * HO];           // Wd as [f][h*16+o], zero rows f>=94
__device__ float g_Wfus[(2 * FEAT + HO) * 64];  // 252x64: [W2a; W2b; W1@W2c]
__device__ float g_b2f[64];                  // b2 + b1@W2c

// ---- dense device-feature table: warp per row, 8 rows per 256-thread block ----
__global__ __launch_bounds__(NTHREADS) void devfeat_kernel(
    const float* __restrict__ device_cont,
    const int*   __restrict__ device_cat,
    const float* __restrict__ de0,
    const float* __restrict__ de1)
{
    const int lane = threadIdx.x & 31;
    const int warp = threadIdx.x >> 5;
    const int row  = blockIdx.x * 8 + warp;
    if (row >= N_DEV) return;

    float* dst = g_dev_feats + (size_t)row * FPAD;

    if (lane < 31) {
        float2 v = *reinterpret_cast<const float2*>(device_cont + (size_t)row * CONT + 2 * lane);
        *reinterpret_cast<float2*>(dst + 2 * lane) = v;
    } else {
        *reinterpret_cast<float2*>(dst + 94) = make_float2(0.f, 0.f);
    }
    if (lane < 8) {
        int n0 = device_cat[2 * row];
        float2 v = *reinterpret_cast<const float2*>(de0 + (size_t)n0 * EMB + 2 * lane);
        *reinterpret_cast<float2*>(dst + 62 + 2 * lane) = v;
    } else if (lane < 16) {
        int n1 = device_cat[2 * row + 1];
        float2 v = *reinterpret_cast<const float2*>(de1 + (size_t)n1 * EMB + 2 * (lane - 8));
        *reinterpret_cast<float2*>(dst + 78 + 2 * (lane - 8)) = v;
    }
}

__global__ __launch_bounds__(NTHREADS) void prep_kernel(
    const float* __restrict__ Wc, const float* __restrict__ bc,
    const float* __restrict__ Wd, const float* __restrict__ bd,
    const float* __restrict__ aW, const float* __restrict__ ab,
    const float* __restrict__ W1, const float* __restrict__ b1,
    const float* __restrict__ W2, const float* __restrict__ b2)
{
    const int tid = threadIdx.x;

    for (int idx = tid; idx < NH * FPAD; idx += NTHREADS) {
        int h = idx / FPAD, f = idx % FPAD;
        float s2 = 0.f, s1 = 0.f;
        if (f < FEAT) {
            #pragma unroll
            for (int o = 0; o < NOUT; o++) {
                s2 += Wd[(h * FEAT + f) * NOUT + o] * aW[h * 2 * NOUT + NOUT + o];
                s1 += Wc[(h * FEAT + f) * NOUT + o] * aW[h * 2 * NOUT + o];
            }
        }
        g_wd2[idx] = s2;
        g_vch[idx] = s1;
    }
    if (tid < NH) {
        float s = ab[tid];
        #pragma unroll
        for (int o = 0; o < NOUT; o++) {
            s += bc[tid * NOUT + o] * aW[tid * 2 * NOUT + o];
            s += bd[tid * NOUT + o] * aW[tid * 2 * NOUT + NOUT + o];
        }
        g_ech[tid] = s;
    }
    for (int idx = tid; idx < FPAD * HO; idx += NTHREADS) {
        int f = idx >> 6, ho = idx & 63;
        g_Wdp[idx] = (f < FEAT) ? Wd[((ho >> 4) * FEAT + f) * NOUT + (ho & 15)] : 0.f;
    }
    for (int idx = tid; idx < (2 * FEAT + HO) * 64; idx += NTHREADS) {
        int r = idx >> 6, j = idx & 63;
        float v;
        if (r < 2 * FEAT) {
            v = W2[r * 64 + j];
        } else {
            int i = r - 2 * FEAT;
            float s = 0.f;
            #pragma unroll
            for (int t = 0; t < NOUT; t++)
                s += W1[i * NOUT + t] * W2[(2 * FEAT + t) * 64 + j];
            v = s;
        }
        g_Wfus[idx] = v;
    }
    if (tid < 64) {
        float s = b2[tid];
        #pragma unroll
        for (int t = 0; t < NOUT; t++)
            s += b1[t] * W2[(2 * FEAT + t) * 64 + tid];
        g_b2f[tid] = s;
    }
}

// ---------------- main fused kernel: one CTA per batch element -------------------
__global__ __launch_bounds__(NTHREADS) void gat_kernel(
    const float* __restrict__ combin_cont,
    const int*   __restrict__ combin_cat,
    const int*   __restrict__ combin_idx,
    const int*   __restrict__ device_idx,
    const int*   __restrict__ neighbor_idx,
    const float* __restrict__ ce0,
    const float* __restrict__ ce1,
    const float* __restrict__ bd,
    const float* __restrict__ W3,
    const float* __restrict__ b3,
    const float* __restrict__ W4,
    const float* __restrict__ b4,
    float* __restrict__ out)
{
    __shared__ __align__(16) float sFeat[KNB * FSTR];   // 25600B
    __shared__ __align__(16) float sWd2[NH * FPAD];     // [h][f]
    __shared__ __align__(16) float sM[NH * FPAD];       // pooled features [h][96]
    __shared__ float sE[NH * KNB];                      // attn [h][k]
    __shared__ float sEbase[NH];
    __shared__ float sComb[FPAD];
    __shared__ float sDev[FPAD];
    __shared__ float sHO[HO];
    __shared__ float sX2[64];
    __shared__ float sPart[3 * 64];
    __shared__ float sP2[4 * 32];
    __shared__ int   sNid[KNB];

    const int b    = blockIdx.x;
    const int tid  = threadIdx.x;
    const int lane = tid & 31;
    const int warp = tid >> 5;

    // ---- Prologue: all independent loads, one phase ----
    if (tid < 96) {
        reinterpret_cast<float4*>(sWd2)[tid] = reinterpret_cast<const float4*>(g_wd2)[tid];
    }
    if (tid < KNB) {
        sNid[tid] = neighbor_idx[b * KNB + tid];
    } else if (tid < 64 + FEAT) {
        int f = tid - 64;
        int ci = combin_idx[b];
        float v;
        if (f < CONT)            v = combin_cont[ci * CONT + f];
        else if (f < CONT + EMB) v = ce0[combin_cat[2 * ci]     * EMB + (f - CONT)];
        else                     v = ce1[combin_cat[2 * ci + 1] * EMB + (f - CONT - EMB)];
        sComb[f] = v;
    } else if (tid >= 160) {
        int f = tid - 160;   // 0..95
        int di = device_idx[b];
        sDev[f] = g_dev_feats[(size_t)di * FPAD + f];
    }
    __syncthreads();

    // ---- Gather (warps 0-6, dense float4 rows) + e_base (warp 7) ----
    if (warp < 7) {
        for (int k = warp; k < KNB; k += 7) {
            const int nid = sNid[k];
            if (lane < 24) {
                float4 v = *reinterpret_cast<const float4*>(g_dev_feats + (size_t)nid * FPAD + 4 * lane);
                *reinterpret_cast<float4*>(sFeat + k * FSTR + 4 * lane) = v;
            }
        }
    } else {
        int h = lane >> 3, sub = lane & 7;
        float s = 0.f;
        for (int f = sub; f < FEAT; f += 8)
            s += sComb[f] * g_vch[h * FPAD + f];
        s += __shfl_down_sync(0xffffffffu, s, 4);
        s += __shfl_down_sync(0xffffffffu, s, 2);
        s += __shfl_down_sync(0xffffffffu, s, 1);
        if (sub == 0) sEbase[h] = s + g_ech[h];
    }
    __syncthreads();

    // ---- S1: e[h][k] = feat_k . wd2[h] + e_base[h], leaky-relu ----
    {
        int k = tid & 63, h = tid >> 6;
        const float4* fp = reinterpret_cast<const float4*>(sFeat) + k * (FSTR / 4);
        const float4* wp = reinterpret_cast<const float4*>(sWd2) + h * (FPAD / 4);
        float ax = 0.f, ay = 0.f, az = 0.f, aw = 0.f;
        #pragma unroll
        for (int ff = 0; ff < FPAD / 4; ff++) {
            float4 a = fp[ff];
            float4 w = wp[ff];
            ax += a.x * w.x; ay += a.y * w.y; az += a.z * w.z; aw += a.w * w.w;
        }
        float e = (ax + ay) + (az + aw) + sEbase[h];
        sE[h * KNB + k] = (e >= 0.f) ? e : 0.2f * e;
    }
    __syncthreads();

    // ---- softmax over k per head (warp h) ----
    if (tid < 128) {
        int h = tid >> 5;
        float v0 = sE[h * KNB + lane];
        float v1 = sE[h * KNB + lane + 32];
        float m = fmaxf(v0, v1);
        #pragma unroll
        for (int off = 16; off; off >>= 1) m = fmaxf(m, __shfl_xor_sync(0xffffffffu, m, off));
        float e0 = __expf(v0 - m), e1 = __expf(v1 - m);
        float s = e0 + e1;
        #pragma unroll
        for (int off = 16; off; off >>= 1) s += __shfl_xor_sync(0xffffffffu, s, off);
        float inv = __frcp_rn(s);
        sE[h * KNB + lane]      = e0 * inv;
        sE[h * KNB + lane + 32] = e1 * inv;
    }
    __syncthreads();

    // ---- S2: pooled features m[h][f] = sum_k attn[h][k] * feat[k][f] ----
    #pragma unroll
    for (int pass = 0; pass < 2; pass++) {
        int idx = pass * NTHREADS + tid;
        if (idx < NH * FPAD) {
            int h = idx / FPAD, f = idx % FPAD;
            float s = 0.f;
            const float* ep = sE + h * KNB;
            const float* fp = sFeat + f;
            #pragma unroll 8
            for (int k = 0; k < KNB; k++)
                s += ep[k] * fp[k * FSTR];
            sM[idx] = s;
        }
    }
    __syncthreads();

    // ---- S3 (threads 0-63): head_out = elu(m[h] @ Wd[h] + bd) || fusion partials ----
    if (tid < HO) {
        int h = tid >> 4;
        float s = bd[tid];
        const float* mp = sM + h * FPAD;
        #pragma unroll 2
        for (int f = 0; f < FEAT; f++)
            s += mp[f] * g_Wdp[f * HO + tid];
        sHO[tid] = (s > 0.f) ? s : (__expf(s) - 1.f);
    } else {
        // threads 64-255: comb/dev part of fusion layer (3 chunks of ~63 rows)
        int t = tid - 64;
        int c = t >> 6, j = t & 63;
        int r0 = c * 63;
        int r1 = (c == 2) ? 2 * FEAT : r0 + 63;
        float s = 0.f;
        for (int r = r0; r < r1; r++) {
            float fv = (r < FEAT) ? sComb[r] : sDev[r - FEAT];
            s += fv * g_Wfus[r * 64 + j];
        }
        sPart[c * 64 + j] = s;
    }
    __syncthreads();

    // ---- S4: x2 = relu(b2f + partials + head_out @ W12) ----
    if (tid < 64) {
        float s = g_b2f[tid] + sPart[tid] + sPart[64 + tid] + sPart[128 + tid];
        #pragma unroll 4
        for (int i = 0; i < HO; i++)
            s += sHO[i] * g_Wfus[(2 * FEAT + i) * 64 + tid];
        sX2[tid] = fmaxf(s, 0.f);
    }
    __syncthreads();

    // ---- S5: x3 = relu(x2 @ W3 + b3) as 4 partial chunks ----
    if (tid < 128) {
        int j = tid & 31, c = tid >> 5;
        float s = 0.f;
        #pragma unroll
        for (int k = c * 16; k < c * 16 + 16; k++)
            s += sX2[k] * W3[k * 32 + j];
        sP2[c * 32 + j] = s;
    }
    __syncthreads();

    if (tid < 32) {
        float x3 = b3[tid] + sP2[tid] + sP2[32 + tid] + sP2[64 + tid] + sP2[96 + tid];
        x3 = fmaxf(x3, 0.f);
        float v = x3 * W4[tid];
        #pragma unroll
        for (int off = 16; off; off >>= 1) v += __shfl_xor_sync(0xffffffffu, v, off);
        if (tid == 0) out[b] = 1.f / (1.f + __expf(-(v + b4[0])));
    }
}

extern "C" void kernel_launch(void* const* d_in, const int* in_sizes, int n_in,
                              void* d_out, int out_size)
{
    (void)in_sizes; (void)n_in; (void)out_size;

    devfeat_kernel<<<(N_DEV + 7) / 8, NTHREADS>>>(
        (const float*)d_in[2],   // device_cont
        (const int*)  d_in[3],   // device_cat
        (const float*)d_in[9],   // de0
        (const float*)d_in[10]); // de1

    prep_kernel<<<1, NTHREADS>>>(
        (const float*)d_in[11],  // Wc
        (const float*)d_in[12],  // bc
        (const float*)d_in[13],  // Wd
        (const float*)d_in[14],  // bd
        (const float*)d_in[15],  // aW
        (const float*)d_in[16],  // ab
        (const float*)d_in[17],  // W1
        (const float*)d_in[18],  // b1
        (const float*)d_in[19],  // W2
        (const float*)d_in[20]); // b2

    gat_kernel<<<N_B, NTHREADS>>>(
        (const float*)d_in[0],   // combin_cont
        (const int*)  d_in[1],   // combin_cat
        (const int*)  d_in[4],   // combin_idx
        (const int*)  d_in[5],   // device_idx
        (const int*)  d_in[6],   // neighbor_idx
        (const float*)d_in[7],   // ce0
        (const float*)d_in[8],   // ce1
        (const float*)d_in[14],  // bd
        (const float*)d_in[21],  // W3
        (const float*)d_in[22],  // b3
        (const float*)d_in[23],  // W4
        (const float*)d_in[24],  // b4
        (float*)d_out);
}

// round 12
// speedup vs baseline: 1.8241x; 1.0096x over previous
#include <cuda_runtime.h>
#include <math.h>

#define N_B      8192
#define N_DEV    100000
#define CONT     62
#define EMB      16
#define FEAT     94
#define FPAD     96
#define KNB      64
#define NH       4
#define NOUT     16
#define HO       64
#define NTHREADS 256
#define FSTR     100   // sFeat row stride in floats
#define NB4      4     // batch elements per CTA

// ---------------- scratch (written per launch, before gat_kernel) ---------------
__device__ float g_dev_feats[N_DEV * FPAD];  // dense padded device features, 38.4MB
__device__ float g_wd2[NH * FPAD];           // Wd[h] @ a2[h], f-padded with zeros
__device__ float g_vch[NH * FPAD];           // Wc[h] @ a1[h], f-padded with zeros
__device__ float g_ech[NH];                  // bc·a1 + ab + bd·a2
__device__ float g_Wdp[FPAD * HO];           // Wd as [f][h*16+o], zero rows f>=94
__device__ float g_Wfus[(2 * FEAT + HO) * 64];  // 252x64: [W2a; W2b; W1@W2c]
__device__ float g_b2f[64];                  // b2 + b1@W2c

// ---- dense device-feature table: warp per row, 8 rows per 256-thread block ----
__global__ __launch_bounds__(NTHREADS) void devfeat_kernel(
    const float* __restrict__ device_cont,
    const int*   __restrict__ device_cat,
    const float* __restrict__ de0,
    const float* __restrict__ de1)
{
    const int lane = threadIdx.x & 31;
    const int warp = threadIdx.x >> 5;
    const int row  = blockIdx.x * 8 + warp;
    if (row >= N_DEV) return;

    float* dst = g_dev_feats + (size_t)row * FPAD;

    if (lane < 31) {
        float2 v = *reinterpret_cast<const float2*>(device_cont + (size_t)row * CONT + 2 * lane);
        *reinterpret_cast<float2*>(dst + 2 * lane) = v;
    } else {
        *reinterpret_cast<float2*>(dst + 94) = make_float2(0.f, 0.f);
    }
    if (lane < 8) {
        int n0 = device_cat[2 * row];
        float2 v = *reinterpret_cast<const float2*>(de0 + (size_t)n0 * EMB + 2 * lane);
        *reinterpret_cast<float2*>(dst + 62 + 2 * lane) = v;
    } else if (lane < 16) {
        int n1 = device_cat[2 * row + 1];
        float2 v = *reinterpret_cast<const float2*>(de1 + (size_t)n1 * EMB + 2 * (lane - 8));
        *reinterpret_cast<float2*>(dst + 78 + 2 * (lane - 8)) = v;
    }
}

__global__ __launch_bounds__(NTHREADS) void prep_kernel(
    const float* __restrict__ Wc, const float* __restrict__ bc,
    const float* __restrict__ Wd, const float* __restrict__ bd,
    const float* __restrict__ aW, const float* __restrict__ ab,
    const float* __restrict__ W1, const float* __restrict__ b1,
    const float* __restrict__ W2, const float* __restrict__ b2)
{
    const int tid = threadIdx.x;

    for (int idx = tid; idx < NH * FPAD; idx += NTHREADS) {
        int h = idx / FPAD, f = idx % FPAD;
        float s2 = 0.f, s1 = 0.f;
        if (f < FEAT) {
            #pragma unroll
            for (int o = 0; o < NOUT; o++) {
                s2 += Wd[(h * FEAT + f) * NOUT + o] * aW[h * 2 * NOUT + NOUT + o];
                s1 += Wc[(h * FEAT + f) * NOUT + o] * aW[h * 2 * NOUT + o];
            }
        }
        g_wd2[idx] = s2;
        g_vch[idx] = s1;
    }
    if (tid < NH) {
        float s = ab[tid];
        #pragma unroll
        for (int o = 0; o < NOUT; o++) {
            s += bc[tid * NOUT + o] * aW[tid * 2 * NOUT + o];
            s += bd[tid * NOUT + o] * aW[tid * 2 * NOUT + NOUT + o];
        }
        g_ech[tid] = s;
    }
    for (int idx = tid; idx < FPAD * HO; idx += NTHREADS) {
        int f = idx >> 6, ho = idx & 63;
        g_Wdp[idx] = (f < FEAT) ? Wd[((ho >> 4) * FEAT + f) * NOUT + (ho & 15)] : 0.f;
    }
    for (int idx = tid; idx < (2 * FEAT + HO) * 64; idx += NTHREADS) {
        int r = idx >> 6, j = idx & 63;
        float v;
        if (r < 2 * FEAT) {
            v = W2[r * 64 + j];
        } else {
            int i = r - 2 * FEAT;
            float s = 0.f;
            #pragma unroll
            for (int t = 0; t < NOUT; t++)
                s += W1[i * NOUT + t] * W2[(2 * FEAT + t) * 64 + j];
            v = s;
        }
        g_Wfus[idx] = v;
    }
    if (tid < 64) {
        float s = b2[tid];
        #pragma unroll
        for (int t = 0; t < NOUT; t++)
            s += b1[t] * W2[(2 * FEAT + t) * 64 + tid];
        g_b2f[tid] = s;
    }
}

// ---------------- main fused kernel: 4 batch elements per CTA --------------------
__global__ __launch_bounds__(NTHREADS) void gat_kernel(
    const float* __restrict__ combin_cont,
    const int*   __restrict__ combin_cat,
    const int*   __restrict__ combin_idx,
    const int*   __restrict__ device_idx,
    const int*   __restrict__ neighbor_idx,
    const float* __restrict__ ce0,
    const float* __restrict__ ce1,
    const float* __restrict__ bd,
    const float* __restrict__ W3,
    const float* __restrict__ b3,
    const float* __restrict__ W4,
    const float* __restrict__ b4,
    float* __restrict__ out)
{
    __shared__ __align__(16) float sFeat[KNB * FSTR];       // 25600B, reused per element
    __shared__ __align__(16) float sWd2[NH * FPAD];         // [h][f]
    __shared__ __align__(16) float sM[NB4 * NH * FPAD];     // pooled feats [e][h][96]
    __shared__ float sE[NH * KNB];                          // attn [h][k], reused
    __shared__ float sEbase[NH];                            // reused
    __shared__ float sComb[NB4 * FPAD];
    __shared__ float sDev[NB4 * FPAD];
    __shared__ float sHO[NB4 * HO];
    __shared__ float sX2[NB4 * 64];
    __shared__ float sP2[NTHREADS];
    __shared__ int   sNid[NB4 * KNB];

    const int b0   = blockIdx.x * NB4;
    const int tid  = threadIdx.x;
    const int lane = tid & 31;
    const int warp = tid >> 5;

    // ---- Prologue: everything for all 4 elements, one phase ----
    if (tid < 96) {
        reinterpret_cast<float4*>(sWd2)[tid] = reinterpret_cast<const float4*>(g_wd2)[tid];
    }
    sNid[tid] = neighbor_idx[b0 * KNB + tid];   // 4*64 = 256, contiguous
    #pragma unroll
    for (int pass = 0; pass < 3; pass++) {
        int idx = pass * NTHREADS + tid;        // 0..767
        int e = idx / 192, s = idx - e * 192;
        int b = b0 + e;
        if (s < 96) {
            int f = s;
            float v = 0.f;
            if (f < FEAT) {
                int ci = combin_idx[b];
                if (f < CONT)            v = combin_cont[ci * CONT + f];
                else if (f < CONT + EMB) v = ce0[combin_cat[2 * ci]     * EMB + (f - CONT)];
                else                     v = ce1[combin_cat[2 * ci + 1] * EMB + (f - CONT - EMB)];
            }
            sComb[e * FPAD + f] = v;
        } else {
            int f = s - 96;
            int di = device_idx[b];
            sDev[e * FPAD + f] = g_dev_feats[(size_t)di * FPAD + f];
        }
    }
    __syncthreads();

    // ================= attention loop over the 4 elements =================
    #pragma unroll 1
    for (int ei = 0; ei < NB4; ei++) {
        // ---- Gather (warps 0-6) + e_base (warp 7) ----
        if (warp < 7) {
            for (int k = warp; k < KNB; k += 7) {
                const int nid = sNid[ei * KNB + k];
                if (lane < 24) {
                    float4 v = *reinterpret_cast<const float4*>(g_dev_feats + (size_t)nid * FPAD + 4 * lane);
                    *reinterpret_cast<float4*>(sFeat + k * FSTR + 4 * lane) = v;
                }
            }
        } else {
            int h = lane >> 3, sub = lane & 7;
            float s = 0.f;
            for (int f = sub; f < FEAT; f += 8)
                s += sComb[ei * FPAD + f] * g_vch[h * FPAD + f];
            s += __shfl_down_sync(0xffffffffu, s, 4);
            s += __shfl_down_sync(0xffffffffu, s, 2);
            s += __shfl_down_sync(0xffffffffu, s, 1);
            if (sub == 0) sEbase[h] = s + g_ech[h];
        }
        __syncthreads();

        // ---- S1: e[h][k] = feat_k . wd2[h] + e_base[h], leaky-relu ----
        {
            int k = tid & 63, h = tid >> 6;
            const float4* fp = reinterpret_cast<const float4*>(sFeat) + k * (FSTR / 4);
            const float4* wp = reinterpret_cast<const float4*>(sWd2) + h * (FPAD / 4);
            float ax = 0.f, ay = 0.f, az = 0.f, aw = 0.f;
            #pragma unroll
            for (int ff = 0; ff < FPAD / 4; ff++) {
                float4 a = fp[ff];
                float4 w = wp[ff];
                ax += a.x * w.x; ay += a.y * w.y; az += a.z * w.z; aw += a.w * w.w;
            }
            float e = (ax + ay) + (az + aw) + sEbase[h];
            sE[h * KNB + k] = (e >= 0.f) ? e : 0.2f * e;
        }
        __syncthreads();

        // ---- softmax over k per head (warp h) ----
        if (tid < 128) {
            int h = tid >> 5;
            float v0 = sE[h * KNB + lane];
            float v1 = sE[h * KNB + lane + 32];
            float m = fmaxf(v0, v1);
            #pragma unroll
            for (int off = 16; off; off >>= 1) m = fmaxf(m, __shfl_xor_sync(0xffffffffu, m, off));
            float e0 = __expf(v0 - m), e1 = __expf(v1 - m);
            float s = e0 + e1;
            #pragma unroll
            for (int off = 16; off; off >>= 1) s += __shfl_xor_sync(0xffffffffu, s, off);
            float inv = __frcp_rn(s);
            sE[h * KNB + lane]      = e0 * inv;
            sE[h * KNB + lane + 32] = e1 * inv;
        }
        __syncthreads();

        // ---- S2: pooled features m[ei][h][f] = sum_k attn[h][k]*feat[k][f] ----
        #pragma unroll
        for (int pass = 0; pass < 2; pass++) {
            int idx = pass * NTHREADS + tid;
            if (idx < NH * FPAD) {
                int h = idx / FPAD, f = idx % FPAD;
                float s = 0.f;
                const float* ep = sE + h * KNB;
                const float* fp = sFeat + f;
                #pragma unroll 8
                for (int k = 0; k < KNB; k++)
                    s += ep[k] * fp[k * FSTR];
                sM[ei * (NH * FPAD) + idx] = s;
            }
        }
        __syncthreads();
    }

    // ---- S3 batched: head_out[e][ho] = elu(m[e][h] @ Wd[h] + bd) ----
    {
        int e = tid >> 6, ho = tid & 63, h = ho >> 4;
        float s = bd[ho];
        const float* mp = sM + e * (NH * FPAD) + h * FPAD;
        #pragma unroll 2
        for (int f = 0; f < FEAT; f++)
            s += mp[f] * g_Wdp[f * HO + ho];
        sHO[e * HO + ho] = (s > 0.f) ? s : (__expf(s) - 1.f);
    }
    __syncthreads();

    // ---- S4 batched: x2[e][j] = relu(b2f + fusion(252 rows) @ Wfus[:,j]) ----
    {
        int e = tid >> 6, j = tid & 63;
        const float* cp = sComb + e * FPAD;
        const float* dp = sDev  + e * FPAD;
        const float* hp = sHO   + e * HO;
        float s = g_b2f[j];
        #pragma unroll 2
        for (int r = 0; r < FEAT; r++)
            s += cp[r] * g_Wfus[r * 64 + j];
        #pragma unroll 2
        for (int r = 0; r < FEAT; r++)
            s += dp[r] * g_Wfus[(FEAT + r) * 64 + j];
        #pragma unroll 4
        for (int r = 0; r < HO; r++)
            s += hp[r] * g_Wfus[(2 * FEAT + r) * 64 + j];
        sX2[e * 64 + j] = fmaxf(s, 0.f);
    }
    __syncthreads();

    // ---- S5 partial: x3[e][j] over k-halves ----
    {
        int e = tid >> 6, c = (tid >> 5) & 1, j = lane;
        float s = 0.f;
        #pragma unroll
        for (int k = c * 32; k < c * 32 + 32; k++)
            s += sX2[e * 64 + k] * W3[k * 32 + j];
        sP2[tid] = s;
    }
    __syncthreads();

    // ---- final: combine halves, W4 dot, sigmoid, write 4 outputs ----
    if (tid < 128) {
        int e = tid >> 5, j = lane;
        float x3 = b3[j] + sP2[e * 64 + j] + sP2[e * 64 + 32 + j];
        x3 = fmaxf(x3, 0.f);
        float v = x3 * W4[j];
        #pragma unroll
        for (int off = 16; off; off >>= 1) v += __shfl_xor_sync(0xffffffffu, v, off);
        if (j == 0) out[b0 + e] = 1.f / (1.f + __expf(-(v + b4[0])));
    }
}

extern "C" void kernel_launch(void* const* d_in, const int* in_sizes, int n_in,
                              void* d_out, int out_size)
{
    (void)in_sizes; (void)n_in; (void)out_size;

    devfeat_kernel<<<(N_DEV + 7) / 8, NTHREADS>>>(
        (const float*)d_in[2],   // device_cont
        (const int*)  d_in[3],   // device_cat
        (const float*)d_in[9],   // de0
        (const float*)d_in[10]); // de1

    prep_kernel<<<1, NTHREADS>>>(
        (const float*)d_in[11],  // Wc
        (const float*)d_in[12],  // bc
        (const float*)d_in[13],  // Wd
        (const float*)d_in[14],  // bd
        (const float*)d_in[15],  // aW
        (const float*)d_in[16],  // ab
        (const float*)d_in[17],  // W1
        (const float*)d_in[18],  // b1
        (const float*)d_in[19],  // W2
        (const float*)d_in[20]); // b2

    gat_kernel<<<N_B / NB4, NTHREADS>>>(
        (const float*)d_in[0],   // combin_cont
        (const int*)  d_in[1],   // combin_cat
        (const int*)  d_in[4],   // combin_idx
        (const int*)  d_in[5],   // device_idx
        (const int*)  d_in[6],   // neighbor_idx
        (const float*)d_in[7],   // ce0
        (const float*)d_in[8],   // ce1
        (const float*)d_in[14],  // bd
        (const float*)d_in[21],  // W3
        (const float*)d_in[22],  // b3
        (const float*)d_in[23],  // W4
        (const float*)d_in[24],  // b4
        (float*)d_out);
}

// round 13
// speedup vs baseline: 2.5407x; 1.3928x over previous
#include <cuda_runtime.h>
#include <math.h>

#define N_B      8192
#define N_DEV    100000
#define CONT     62
#define EMB      16
#define FEAT     94
#define FPAD     96
#define KNB      64
#define NH       4
#define NOUT     16
#define HO       64
#define NTHREADS 256
#define FSTR     100   // sFeat row stride in floats
#define NB4      4     // batch elements per CTA
#define MSTR     100   // sM per-head stride (conflict-free h-multicast)

// ---------------- scratch (written per launch, before gat_kernel) ---------------
__device__ float g_dev_feats[N_DEV * FPAD];  // dense padded device features
__device__ float g_wd2[NH * FPAD];           // Wd[h] @ a2[h]
__device__ float g_vch[NH * FPAD];           // Wc[h] @ a1[h]
__device__ float g_ech[NH];                  // bc·a1 + ab + bd·a2
__device__ float g_Wdp[FPAD * HO];           // Wd as [f][h*16+o], zero rows f>=94
__device__ float g_Wfus[256 * 64];           // padded 256x64: [comb96; dev96; HO64]
__device__ float g_b2f[64];                  // b2 + b1@W2c

// ---- dense device-feature table: warp per row, 8 rows per 256-thread block ----
__global__ __launch_bounds__(NTHREADS) void devfeat_kernel(
    const float* __restrict__ device_cont,
    const int*   __restrict__ device_cat,
    const float* __restrict__ de0,
    const float* __restrict__ de1)
{
    const int lane = threadIdx.x & 31;
    const int warp = threadIdx.x >> 5;
    const int row  = blockIdx.x * 8 + warp;
    if (row >= N_DEV) return;

    float* dst = g_dev_feats + (size_t)row * FPAD;

    if (lane < 31) {
        float2 v = *reinterpret_cast<const float2*>(device_cont + (size_t)row * CONT + 2 * lane);
        *reinterpret_cast<float2*>(dst + 2 * lane) = v;
    } else {
        *reinterpret_cast<float2*>(dst + 94) = make_float2(0.f, 0.f);
    }
    if (lane < 8) {
        int n0 = device_cat[2 * row];
        float2 v = *reinterpret_cast<const float2*>(de0 + (size_t)n0 * EMB + 2 * lane);
        *reinterpret_cast<float2*>(dst + 62 + 2 * lane) = v;
    } else if (lane < 16) {
        int n1 = device_cat[2 * row + 1];
        float2 v = *reinterpret_cast<const float2*>(de1 + (size_t)n1 * EMB + 2 * (lane - 8));
        *reinterpret_cast<float2*>(dst + 78 + 2 * (lane - 8)) = v;
    }
}

__global__ __launch_bounds__(NTHREADS) void prep_kernel(
    const float* __restrict__ Wc, const float* __restrict__ bc,
    const float* __restrict__ Wd, const float* __restrict__ bd,
    const float* __restrict__ aW, const float* __restrict__ ab,
    const float* __restrict__ W1, const float* __restrict__ b1,
    const float* __restrict__ W2, const float* __restrict__ b2)
{
    const int tid = threadIdx.x;

    for (int idx = tid; idx < NH * FPAD; idx += NTHREADS) {
        int h = idx / FPAD, f = idx % FPAD;
        float s2 = 0.f, s1 = 0.f;
        if (f < FEAT) {
            #pragma unroll
            for (int o = 0; o < NOUT; o++) {
                s2 += Wd[(h * FEAT + f) * NOUT + o] * aW[h * 2 * NOUT + NOUT + o];
                s1 += Wc[(h * FEAT + f) * NOUT + o] * aW[h * 2 * NOUT + o];
            }
        }
        g_wd2[idx] = s2;
        g_vch[idx] = s1;
    }
    if (tid < NH) {
        float s = ab[tid];
        #pragma unroll
        for (int o = 0; o < NOUT; o++) {
            s += bc[tid * NOUT + o] * aW[tid * 2 * NOUT + o];
            s += bd[tid * NOUT + o] * aW[tid * 2 * NOUT + NOUT + o];
        }
        g_ech[tid] = s;
    }
    for (int idx = tid; idx < FPAD * HO; idx += NTHREADS) {
        int f = idx >> 6, ho = idx & 63;
        g_Wdp[idx] = (f < FEAT) ? Wd[((ho >> 4) * FEAT + f) * NOUT + (ho & 15)] : 0.f;
    }
    // g_Wfus padded layout: rows 0..93 comb (W2 rows 0..93), 94..95 zero,
    // 96..189 dev (W2 rows 94..187), 190..191 zero, 192..255 HO (W1@W2c fold)
    for (int idx = tid; idx < 256 * 64; idx += NTHREADS) {
        int r = idx >> 6, j = idx & 63;
        float v = 0.f;
        if (r < FEAT) {
            v = W2[r * 64 + j];
        } else if (r >= 96 && r < 96 + FEAT) {
            v = W2[(r - 96 + FEAT) * 64 + j];
        } else if (r >= 192) {
            int i = r - 192;
            float s = 0.f;
            #pragma unroll
            for (int t = 0; t < NOUT; t++)
                s += W1[i * NOUT + t] * W2[(2 * FEAT + t) * 64 + j];
            v = s;
        }
        g_Wfus[idx] = v;
    }
    if (tid < 64) {
        float s = b2[tid];
        #pragma unroll
        for (int t = 0; t < NOUT; t++)
            s += b1[t] * W2[(2 * FEAT + t) * 64 + tid];
        g_b2f[tid] = s;
    }
}

// ---------------- main fused kernel: 4 batch elements per CTA --------------------
__global__ __launch_bounds__(NTHREADS) void gat_kernel(
    const float* __restrict__ combin_cont,
    const int*   __restrict__ combin_cat,
    const int*   __restrict__ combin_idx,
    const int*   __restrict__ device_idx,
    const int*   __restrict__ neighbor_idx,
    const float* __restrict__ ce0,
    const float* __restrict__ ce1,
    const float* __restrict__ bd,
    const float* __restrict__ W3,
    const float* __restrict__ b3,
    const float* __restrict__ W4,
    const float* __restrict__ b4,
    float* __restrict__ out)
{
    __shared__ __align__(16) float sFeat[KNB * FSTR];       // reused: post-loop partials live here
    __shared__ __align__(16) float sWd2[NH * FPAD];
    __shared__ __align__(16) float sM[NB4 * NH * MSTR];     // pooled feats [e][h][100-stride]
    __shared__ __align__(16) float sFus[NB4 * 256];         // [e][comb96|dev96|HO64]
    __shared__ float sE[NH * KNB];
    __shared__ float sEbase[NH];
    __shared__ float sX2[NB4 * 64];
    __shared__ float sP2[NTHREADS];
    __shared__ int   sNid[NB4 * KNB];

    const int b0   = blockIdx.x * NB4;
    const int tid  = threadIdx.x;
    const int lane = tid & 31;
    const int warp = tid >> 5;

    // post-loop partial buffers aliased into sFeat (dead after attention loop)
    float4* sP3 = reinterpret_cast<float4*>(sFeat);          // [ (e*16+ho4)*4 + fc ]
    float4* sP4 = reinterpret_cast<float4*>(sFeat + 1024);   // [ (e*16+j4)*4 + rc ]

    // ---- Prologue: everything for all 4 elements, one phase ----
    if (tid < 96) {
        reinterpret_cast<float4*>(sWd2)[tid] = reinterpret_cast<const float4*>(g_wd2)[tid];
    }
    sNid[tid] = neighbor_idx[b0 * KNB + tid];
    #pragma unroll
    for (int pass = 0; pass < 3; pass++) {
        int idx = pass * NTHREADS + tid;        // 0..767
        int e = idx / 192, s = idx - e * 192;
        int b = b0 + e;
        float v = 0.f;
        if (s < 96) {
            int f = s;
            if (f < FEAT) {
                int ci = combin_idx[b];
                if (f < CONT)            v = combin_cont[ci * CONT + f];
                else if (f < CONT + EMB) v = ce0[combin_cat[2 * ci]     * EMB + (f - CONT)];
                else                     v = ce1[combin_cat[2 * ci + 1] * EMB + (f - CONT - EMB)];
            }
        } else {
            int f = s - 96;
            int di = device_idx[b];
            v = g_dev_feats[(size_t)di * FPAD + f];
        }
        sFus[e * 256 + s] = v;
    }
    __syncthreads();

    // ================= attention loop over the 4 elements =================
    #pragma unroll 1
    for (int ei = 0; ei < NB4; ei++) {
        // ---- Gather (warps 0-6) + e_base (warp 7) ----
        if (warp < 7) {
            for (int k = warp; k < KNB; k += 7) {
                const int nid = sNid[ei * KNB + k];
                if (lane < 24) {
                    float4 v = *reinterpret_cast<const float4*>(g_dev_feats + (size_t)nid * FPAD + 4 * lane);
                    *reinterpret_cast<float4*>(sFeat + k * FSTR + 4 * lane) = v;
                }
            }
        } else {
            int h = lane >> 3, sub = lane & 7;
            float s = 0.f;
            for (int f = sub; f < FEAT; f += 8)
                s += sFus[ei * 256 + f] * g_vch[h * FPAD + f];
            s += __shfl_down_sync(0xffffffffu, s, 4);
            s += __shfl_down_sync(0xffffffffu, s, 2);
            s += __shfl_down_sync(0xffffffffu, s, 1);
            if (sub == 0) sEbase[h] = s + g_ech[h];
        }
        __syncthreads();

        // ---- S1: e[h][k] = feat_k . wd2[h] + e_base[h], leaky-relu ----
        {
            int k = tid & 63, h = tid >> 6;
            const float4* fp = reinterpret_cast<const float4*>(sFeat) + k * (FSTR / 4);
            const float4* wp = reinterpret_cast<const float4*>(sWd2) + h * (FPAD / 4);
            float ax = 0.f, ay = 0.f, az = 0.f, aw = 0.f;
            #pragma unroll
            for (int ff = 0; ff < FPAD / 4; ff++) {
                float4 a = fp[ff];
                float4 w = wp[ff];
                ax += a.x * w.x; ay += a.y * w.y; az += a.z * w.z; aw += a.w * w.w;
            }
            float e = (ax + ay) + (az + aw) + sEbase[h];
            sE[h * KNB + k] = (e >= 0.f) ? e : 0.2f * e;
        }
        __syncthreads();

        // ---- softmax over k per head (warp h) ----
        if (tid < 128) {
            int h = tid >> 5;
            float v0 = sE[h * KNB + lane];
            float v1 = sE[h * KNB + lane + 32];
            float m = fmaxf(v0, v1);
            #pragma unroll
            for (int off = 16; off; off >>= 1) m = fmaxf(m, __shfl_xor_sync(0xffffffffu, m, off));
            float e0 = __expf(v0 - m), e1 = __expf(v1 - m);
            float s = e0 + e1;
            #pragma unroll
            for (int off = 16; off; off >>= 1) s += __shfl_xor_sync(0xffffffffu, s, off);
            float inv = __frcp_rn(s);
            sE[h * KNB + lane]      = e0 * inv;
            sE[h * KNB + lane + 32] = e1 * inv;
        }
        __syncthreads();

        // ---- S2: pooled features m[ei][h][f] = sum_k attn[h][k]*feat[k][f] ----
        #pragma unroll
        for (int pass = 0; pass < 2; pass++) {
            int idx = pass * NTHREADS + tid;
            if (idx < NH * FPAD) {
                int h = idx / FPAD, f = idx % FPAD;
                float s = 0.f;
                const float* ep = sE + h * KNB;
                const float* fp = sFeat + f;
                #pragma unroll 8
                for (int k = 0; k < KNB; k++)
                    s += ep[k] * fp[k * FSTR];
                sM[ei * (NH * MSTR) + h * MSTR + f] = s;
            }
        }
        __syncthreads();
    }

    // ---- S3 partial: thread (e, fc, ho4): 24 f x 4 ho, float4 weights ----
    {
        int e = tid >> 6, fc = (tid >> 4) & 3, ho4 = tid & 15;
        int h = ho4 >> 2;
        const float* mp = sM + e * (NH * MSTR) + h * MSTR + fc * 24;
        const float4* wdp = reinterpret_cast<const float4*>(g_Wdp);
        float4 acc = make_float4(0.f, 0.f, 0.f, 0.f);
        #pragma unroll 4
        for (int i = 0; i < 24; i++) {
            int f = fc * 24 + i;
            float m = mp[i];
            float4 w = wdp[f * 16 + ho4];
            acc.x += m * w.x; acc.y += m * w.y; acc.z += m * w.z; acc.w += m * w.w;
        }
        sP3[(e * 16 + ho4) * 4 + fc] = acc;
    }
    __syncthreads();

    // ---- S3 combine: head_out -> sFus[e][192..255] (elu) ----
    if (tid < 64) {
        int e = tid >> 4, ho4 = tid & 15;
        float4 a = sP3[(e * 16 + ho4) * 4 + 0];
        float4 b = sP3[(e * 16 + ho4) * 4 + 1];
        float4 c = sP3[(e * 16 + ho4) * 4 + 2];
        float4 d = sP3[(e * 16 + ho4) * 4 + 3];
        float4 bdv = reinterpret_cast<const float4*>(bd)[ho4];
        float r0 = a.x + b.x + c.x + d.x + bdv.x;
        float r1 = a.y + b.y + c.y + d.y + bdv.y;
        float r2 = a.z + b.z + c.z + d.z + bdv.z;
        float r3 = a.w + b.w + c.w + d.w + bdv.w;
        float* dst = sFus + e * 256 + 192 + 4 * ho4;
        dst[0] = (r0 > 0.f) ? r0 : (__expf(r0) - 1.f);
        dst[1] = (r1 > 0.f) ? r1 : (__expf(r1) - 1.f);
        dst[2] = (r2 > 0.f) ? r2 : (__expf(r2) - 1.f);
        dst[3] = (r3 > 0.f) ? r3 : (__expf(r3) - 1.f);
    }
    __syncthreads();

    // ---- S4 partial: thread (e, rc, j4): 64 rows x 4 j, float4 weights ----
    {
        int e = tid >> 6, rc = (tid >> 4) & 3, j4 = tid & 15;
        const float* fp = sFus + e * 256 + rc * 64;
        const float4* wf = reinterpret_cast<const float4*>(g_Wfus) + rc * 64 * 16 + j4;
        float4 acc = make_float4(0.f, 0.f, 0.f, 0.f);
        #pragma unroll 4
        for (int i = 0; i < 64; i++) {
            float fv = fp[i];
            float4 w = wf[i * 16];
            acc.x += fv * w.x; acc.y += fv * w.y; acc.z += fv * w.z; acc.w += fv * w.w;
        }
        sP4[(e * 16 + j4) * 4 + rc] = acc;
    }
    __syncthreads();

    // ---- S4 combine: x2 = relu(b2f + sum of rc partials) ----
    if (tid < 64) {
        int e = tid >> 4, j4 = tid & 15;
        float4 a = sP4[(e * 16 + j4) * 4 + 0];
        float4 b = sP4[(e * 16 + j4) * 4 + 1];
        float4 c = sP4[(e * 16 + j4) * 4 + 2];
        float4 d = sP4[(e * 16 + j4) * 4 + 3];
        float4 bb = reinterpret_cast<const float4*>(g_b2f)[j4];
        float* dst = sX2 + e * 64 + 4 * j4;
        dst[0] = fmaxf(a.x + b.x + c.x + d.x + bb.x, 0.f);
        dst[1] = fmaxf(a.y + b.y + c.y + d.y + bb.y, 0.f);
        dst[2] = fmaxf(a.z + b.z + c.z + d.z + bb.z, 0.f);
        dst[3] = fmaxf(a.w + b.w + c.w + d.w + bb.w, 0.f);
    }
    __syncthreads();

    // ---- S5 partial: x3[e][j] over k-halves ----
    {
        int e = tid >> 6, c = (tid >> 5) & 1, j = lane;
        float s = 0.f;
        #pragma unroll
        for (int k = c * 32; k < c * 32 + 32; k++)
            s += sX2[e * 64 + k] * W3[k * 32 + j];
        sP2[tid] = s;
    }
    __syncthreads();

    // ---- final: combine halves, W4 dot, sigmoid, write 4 outputs ----
    if (tid < 128) {
        int e = tid >> 5, j = lane;
        float x3 = b3[j] + sP2[e * 64 + j] + sP2[e * 64 + 32 + j];
        x3 = fmaxf(x3, 0.f);
        float v = x3 * W4[j];
        #pragma unroll
        for (int off = 16; off; off >>= 1) v += __shfl_xor_sync(0xffffffffu, v, off);
        if (j == 0) out[b0 + e] = 1.f / (1.f + __expf(-(v + b4[0])));
    }
}

extern "C" void kernel_launch(void* const* d_in, const int* in_sizes, int n_in,
                              void* d_out, int out_size)
{
    (void)in_sizes; (void)n_in; (void)out_size;

    devfeat_kernel<<<(N_DEV + 7) / 8, NTHREADS>>>(
        (const float*)d_in[2],   // device_cont
        (const int*)  d_in[3],   // device_cat
        (const float*)d_in[9],   // de0
        (const float*)d_in[10]); // de1

    prep_kernel<<<1, NTHREADS>>>(
        (const float*)d_in[11],  // Wc
        (const float*)d_in[12],  // bc
        (const float*)d_in[13],  // Wd
        (const float*)d_in[14],  // bd
        (const float*)d_in[15],  // aW
        (const float*)d_in[16],  // ab
        (const float*)d_in[17],  // W1
        (const float*)d_in[18],  // b1
        (const float*)d_in[19],  // W2
        (const float*)d_in[20]); // b2

    gat_kernel<<<N_B / NB4, NTHREADS>>>(
        (const float*)d_in[0],   // combin_cont
        (const int*)  d_in[1],   // combin_cat
        (const int*)  d_in[4],   // combin_idx
        (const int*)  d_in[5],   // device_idx
        (const int*)  d_in[6],   // neighbor_idx
        (const float*)d_in[7],   // ce0
        (const float*)d_in[8],   // ce1
        (const float*)d_in[14],  // bd
        (const float*)d_in[21],  // W3
        (const float*)d_in[22],  // b3
        (const float*)d_in[23],  // W4
        (const float*)d_in[24],  // b4
        (float*)d_out);
}

// round 14
// speedup vs baseline: 2.5428x; 1.0008x over previous
#include <cuda_runtime.h>
#include <math.h>

#define N_B      8192
#define N_DEV    100000
#define CONT     62
#define EMB      16
#define FEAT     94
#define FPAD     96
#define KNB      64
#define NH       4
#define NOUT     16
#define HO       64
#define NTHREADS 256
#define FSTR     100   // sFeat row stride in floats
#define NB4      4     // batch elements per CTA
#define MSTR     100   // sM per-head stride

// ---------------- scratch (written per launch, before gat_kernel) ---------------
__device__ float g_dev_feats[N_DEV * FPAD];  // dense padded device features
__device__ float g_wd2[NH * FPAD];           // Wd[h] @ a2[h]
__device__ float g_vch[NH * FPAD];           // Wc[h] @ a1[h]
__device__ float g_ech[NH];                  // bc·a1 + ab + bd·a2
__device__ float g_Wdp[FPAD * HO];           // Wd as [f][h*16+o], zero rows f>=94
__device__ float g_Wfus[256 * 64];           // padded 256x64: [comb96; dev96; HO64]
__device__ float g_b2f[64];                  // b2 + b1@W2c

// ---- dense device-feature table: warp per row, 8 rows per 256-thread block ----
__global__ __launch_bounds__(NTHREADS) void devfeat_kernel(
    const float* __restrict__ device_cont,
    const int*   __restrict__ device_cat,
    const float* __restrict__ de0,
    const float* __restrict__ de1)
{
    const int lane = threadIdx.x & 31;
    const int warp = threadIdx.x >> 5;
    const int row  = blockIdx.x * 8 + warp;
    if (row >= N_DEV) return;

    float* dst = g_dev_feats + (size_t)row * FPAD;

    if (lane < 31) {
        float2 v = *reinterpret_cast<const float2*>(device_cont + (size_t)row * CONT + 2 * lane);
        *reinterpret_cast<float2*>(dst + 2 * lane) = v;
    } else {
        *reinterpret_cast<float2*>(dst + 94) = make_float2(0.f, 0.f);
    }
    if (lane < 8) {
        int n0 = device_cat[2 * row];
        float2 v = *reinterpret_cast<const float2*>(de0 + (size_t)n0 * EMB + 2 * lane);
        *reinterpret_cast<float2*>(dst + 62 + 2 * lane) = v;
    } else if (lane < 16) {
        int n1 = device_cat[2 * row + 1];
        float2 v = *reinterpret_cast<const float2*>(de1 + (size_t)n1 * EMB + 2 * (lane - 8));
        *reinterpret_cast<float2*>(dst + 78 + 2 * (lane - 8)) = v;
    }
}

__global__ __launch_bounds__(NTHREADS) void prep_kernel(
    const float* __restrict__ Wc, const float* __restrict__ bc,
    const float* __restrict__ Wd, const float* __restrict__ bd,
    const float* __restrict__ aW, const float* __restrict__ ab,
    const float* __restrict__ W1, const float* __restrict__ b1,
    const float* __restrict__ W2, const float* __restrict__ b2)
{
    const int tid = threadIdx.x;

    for (int idx = tid; idx < NH * FPAD; idx += NTHREADS) {
        int h = idx / FPAD, f = idx % FPAD;
        float s2 = 0.f, s1 = 0.f;
        if (f < FEAT) {
            #pragma unroll
            for (int o = 0; o < NOUT; o++) {
                s2 += Wd[(h * FEAT + f) * NOUT + o] * aW[h * 2 * NOUT + NOUT + o];
                s1 += Wc[(h * FEAT + f) * NOUT + o] * aW[h * 2 * NOUT + o];
            }
        }
        g_wd2[idx] = s2;
        g_vch[idx] = s1;
    }
    if (tid < NH) {
        float s = ab[tid];
        #pragma unroll
        for (int o = 0; o < NOUT; o++) {
            s += bc[tid * NOUT + o] * aW[tid * 2 * NOUT + o];
            s += bd[tid * NOUT + o] * aW[tid * 2 * NOUT + NOUT + o];
        }
        g_ech[tid] = s;
    }
    for (int idx = tid; idx < FPAD * HO; idx += NTHREADS) {
        int f = idx >> 6, ho = idx & 63;
        g_Wdp[idx] = (f < FEAT) ? Wd[((ho >> 4) * FEAT + f) * NOUT + (ho & 15)] : 0.f;
    }
    // g_Wfus padded layout: rows 0..93 comb, 96..189 dev, 192..255 HO-fold
    for (int idx = tid; idx < 256 * 64; idx += NTHREADS) {
        int r = idx >> 6, j = idx & 63;
        float v = 0.f;
        if (r < FEAT) {
            v = W2[r * 64 + j];
        } else if (r >= 96 && r < 96 + FEAT) {
            v = W2[(r - 96 + FEAT) * 64 + j];
        } else if (r >= 192) {
            int i = r - 192;
            float s = 0.f;
            #pragma unroll
            for (int t = 0; t < NOUT; t++)
                s += W1[i * NOUT + t] * W2[(2 * FEAT + t) * 64 + j];
            v = s;
        }
        g_Wfus[idx] = v;
    }
    if (tid < 64) {
        float s = b2[tid];
        #pragma unroll
        for (int t = 0; t < NOUT; t++)
            s += b1[t] * W2[(2 * FEAT + t) * 64 + tid];
        g_b2f[tid] = s;
    }
}

// ---------------- main fused kernel: 4 batch elements per CTA --------------------
__global__ __launch_bounds__(NTHREADS) void gat_kernel(
    const float* __restrict__ combin_cont,
    const int*   __restrict__ combin_cat,
    const int*   __restrict__ combin_idx,
    const int*   __restrict__ device_idx,
    const int*   __restrict__ neighbor_idx,
    const float* __restrict__ ce0,
    const float* __restrict__ ce1,
    const float* __restrict__ bd,
    const float* __restrict__ W3,
    const float* __restrict__ b3,
    const float* __restrict__ W4,
    const float* __restrict__ b4,
    float* __restrict__ out)
{
    __shared__ __align__(16) float sFeat[KNB * FSTR];       // reused; post-loop partials alias here
    __shared__ __align__(16) float sWd2[NH * FPAD];
    __shared__ __align__(16) float sM[NB4 * NH * MSTR];     // pooled feats [e][h][100-stride]
    __shared__ __align__(16) float sFus[NB4 * 256];         // [e][comb96|dev96|HO64]
    __shared__ __align__(16) float sScratch[768];           // sMp (loop) / sX2+sP2 (post-loop)
    __shared__ float sE[NH * KNB];
    __shared__ float sEbase[NH];
    __shared__ int   sNid[NB4 * KNB];

    const int b0   = blockIdx.x * NB4;
    const int tid  = threadIdx.x;
    const int lane = tid & 31;
    const int warp = tid >> 5;

    float4* sMp = reinterpret_cast<float4*>(sScratch);       // [192] during attention loop
    float*  sX2 = sScratch;                                   // [256] post-loop
    float*  sP2 = sScratch + 256;                             // [256] post-loop
    float4* sP3 = reinterpret_cast<float4*>(sFeat);           // [ (e*16+ho4)*4 + fc ]
    float4* sP4 = reinterpret_cast<float4*>(sFeat + 1024);    // [ (e*16+j4)*4 + rc ]

    // ---- Prologue: everything for all 4 elements, one phase ----
    if (tid < 96) {
        reinterpret_cast<float4*>(sWd2)[tid] = reinterpret_cast<const float4*>(g_wd2)[tid];
    }
    sNid[tid] = neighbor_idx[b0 * KNB + tid];
    #pragma unroll
    for (int pass = 0; pass < 3; pass++) {
        int idx = pass * NTHREADS + tid;        // 0..767
        int e = idx / 192, s = idx - e * 192;
        int b = b0 + e;
        float v = 0.f;
        if (s < 96) {
            int f = s;
            if (f < FEAT) {
                int ci = combin_idx[b];
                if (f < CONT)            v = combin_cont[ci * CONT + f];
                else if (f < CONT + EMB) v = ce0[combin_cat[2 * ci]     * EMB + (f - CONT)];
                else                     v = ce1[combin_cat[2 * ci + 1] * EMB + (f - CONT - EMB)];
            }
        } else {
            int f = s - 96;
            int di = device_idx[b];
            v = g_dev_feats[(size_t)di * FPAD + f];
        }
        sFus[e * 256 + s] = v;
    }
    __syncthreads();

    // ================= attention loop over the 4 elements =================
    #pragma unroll 1
    for (int ei = 0; ei < NB4; ei++) {
        // ---- Gather (warps 0-6) + e_base (warp 7) ----
        if (warp < 7) {
            for (int k = warp; k < KNB; k += 7) {
                const int nid = sNid[ei * KNB + k];
                if (lane < 24) {
                    float4 v = *reinterpret_cast<const float4*>(g_dev_feats + (size_t)nid * FPAD + 4 * lane);
                    *reinterpret_cast<float4*>(sFeat + k * FSTR + 4 * lane) = v;
                }
            }
        } else {
            int h = lane >> 3, sub = lane & 7;
            float s = 0.f;
            for (int f = sub; f < FEAT; f += 8)
                s += sFus[ei * 256 + f] * g_vch[h * FPAD + f];
            s += __shfl_down_sync(0xffffffffu, s, 4);
            s += __shfl_down_sync(0xffffffffu, s, 2);
            s += __shfl_down_sync(0xffffffffu, s, 1);
            if (sub == 0) sEbase[h] = s + g_ech[h];
        }
        __syncthreads();

        // ---- S1: e[h][k] = feat_k . wd2[h] + e_base[h], leaky-relu ----
        {
            int k = tid & 63, h = tid >> 6;
            const float4* fp = reinterpret_cast<const float4*>(sFeat) + k * (FSTR / 4);
            const float4* wp = reinterpret_cast<const float4*>(sWd2) + h * (FPAD / 4);
            float ax = 0.f, ay = 0.f, az = 0.f, aw = 0.f;
            #pragma unroll
            for (int ff = 0; ff < FPAD / 4; ff++) {
                float4 a = fp[ff];
                float4 w = wp[ff];
                ax += a.x * w.x; ay += a.y * w.y; az += a.z * w.z; aw += a.w * w.w;
            }
            float e = (ax + ay) + (az + aw) + sEbase[h];
            sE[h * KNB + k] = (e >= 0.f) ? e : 0.2f * e;
        }
        __syncthreads();

        // ---- softmax over k per head (warp h) ----
        if (tid < 128) {
            int h = tid >> 5;
            float v0 = sE[h * KNB + lane];
            float v1 = sE[h * KNB + lane + 32];
            float m = fmaxf(v0, v1);
            #pragma unroll
            for (int off = 16; off; off >>= 1) m = fmaxf(m, __shfl_xor_sync(0xffffffffu, m, off));
            float e0 = __expf(v0 - m), e1 = __expf(v1 - m);
            float s = e0 + e1;
            #pragma unroll
            for (int off = 16; off; off >>= 1) s += __shfl_xor_sync(0xffffffffu, s, off);
            float inv = __frcp_rn(s);
            sE[h * KNB + lane]      = e0 * inv;
            sE[h * KNB + lane + 32] = e1 * inv;
        }
        __syncthreads();

        // ---- S2 partial: thread (kc, h, f4): float4 over 32-k half ----
        if (tid < 192) {
            int kc = tid / 96;
            int r  = tid - kc * 96;
            int h  = r / 24, f4 = r - h * 24;
            const float4* fp4 = reinterpret_cast<const float4*>(sFeat) + f4;
            const float*  ep  = sE + h * KNB + kc * 32;
            float4 acc = make_float4(0.f, 0.f, 0.f, 0.f);
            #pragma unroll 8
            for (int i = 0; i < 32; i++) {
                float ev = ep[i];
                float4 a = fp4[(kc * 32 + i) * (FSTR / 4)];
                acc.x += ev * a.x; acc.y += ev * a.y; acc.z += ev * a.z; acc.w += ev * a.w;
            }
            sMp[tid] = acc;
        }
        __syncthreads();

        // ---- S2 combine: sM[e][h][f4] = p(kc=0) + p(kc=1) ----
        if (tid < 96) {
            int h = tid / 24, f4 = tid - h * 24;
            float4 a = sMp[tid], b = sMp[96 + tid];
            float4 r = make_float4(a.x + b.x, a.y + b.y, a.z + b.z, a.w + b.w);
            *reinterpret_cast<float4*>(sM + ei * (NH * MSTR) + h * MSTR + 4 * f4) = r;
        }
        __syncthreads();
    }

    // ---- S3 partial: thread (e, fc, ho4): 24 f x 4 ho, float4 weights ----
    {
        int e = tid >> 6, fc = (tid >> 4) & 3, ho4 = tid & 15;
        int h = ho4 >> 2;
        const float* mp = sM + e * (NH * MSTR) + h * MSTR + fc * 24;
        const float4* wdp = reinterpret_cast<const float4*>(g_Wdp);
        float4 acc = make_float4(0.f, 0.f, 0.f, 0.f);
        #pragma unroll 4
        for (int i = 0; i < 24; i++) {
            int f = fc * 24 + i;
            float m = mp[i];
            float4 w = wdp[f * 16 + ho4];
            acc.x += m * w.x; acc.y += m * w.y; acc.z += m * w.z; acc.w += m * w.w;
        }
        sP3[(e * 16 + ho4) * 4 + fc] = acc;
    }
    __syncthreads();

    // ---- S3 combine: head_out -> sFus[e][192..255] (elu) ----
    if (tid < 64) {
        int e = tid >> 4, ho4 = tid & 15;
        float4 a = sP3[(e * 16 + ho4) * 4 + 0];
        float4 b = sP3[(e * 16 + ho4) * 4 + 1];
        float4 c = sP3[(e * 16 + ho4) * 4 + 2];
        float4 d = sP3[(e * 16 + ho4) * 4 + 3];
        float4 bdv = reinterpret_cast<const float4*>(bd)[ho4];
        float r0 = a.x + b.x + c.x + d.x + bdv.x;
        float r1 = a.y + b.y + c.y + d.y + bdv.y;
        float r2 = a.z + b.z + c.z + d.z + bdv.z;
        float r3 = a.w + b.w + c.w + d.w + bdv.w;
        float* dst = sFus + e * 256 + 192 + 4 * ho4;
        dst[0] = (r0 > 0.f) ? r0 : (__expf(r0) - 1.f);
        dst[1] = (r1 > 0.f) ? r1 : (__expf(r1) - 1.f);
        dst[2] = (r2 > 0.f) ? r2 : (__expf(r2) - 1.f);
        dst[3] = (r3 > 0.f) ? r3 : (__expf(r3) - 1.f);
    }
    __syncthreads();

    // ---- S4 partial: thread (e, rc, j4): 64 rows x 4 j, float4 weights ----
    {
        int e = tid >> 6, rc = (tid >> 4) & 3, j4 = tid & 15;
        const float* fp = sFus + e * 256 + rc * 64;
        const float4* wf = reinterpret_cast<const float4*>(g_Wfus) + rc * 64 * 16 + j4;
        float4 acc = make_float4(0.f, 0.f, 0.f, 0.f);
        #pragma unroll 4
        for (int i = 0; i < 64; i++) {
            float fv = fp[i];
            float4 w = wf[i * 16];
            acc.x += fv * w.x; acc.y += fv * w.y; acc.z += fv * w.z; acc.w += fv * w.w;
        }
        sP4[(e * 16 + j4) * 4 + rc] = acc;
    }
    __syncthreads();

    // ---- S4 combine: x2 = relu(b2f + sum of rc partials) ----
    if (tid < 64) {
        int e = tid >> 4, j4 = tid & 15;
        float4 a = sP4[(e * 16 + j4) * 4 + 0];
        float4 b = sP4[(e * 16 + j4) * 4 + 1];
        float4 c = sP4[(e * 16 + j4) * 4 + 2];
        float4 d = sP4[(e * 16 + j4) * 4 + 3];
        float4 bb = reinterpret_cast<const float4*>(g_b2f)[j4];
        float* dst = sX2 + e * 64 + 4 * j4;
        dst[0] = fmaxf(a.x + b.x + c.x + d.x + bb.x, 0.f);
        dst[1] = fmaxf(a.y + b.y + c.y + d.y + bb.y, 0.f);
        dst[2] = fmaxf(a.z + b.z + c.z + d.z + bb.z, 0.f);
        dst[3] = fmaxf(a.w + b.w + c.w + d.w + bb.w, 0.f);
    }
    __syncthreads();

    // ---- S5 partial: x3[e][j] over k-halves ----
    {
        int e = tid >> 6, c = (tid >> 5) & 1, j = lane;
        float s = 0.f;
        #pragma unroll
        for (int k = c * 32; k < c * 32 + 32; k++)
            s += sX2[e * 64 + k] * W3[k * 32 + j];
        sP2[tid] = s;
    }
    __syncthreads();

    // ---- final: combine halves, W4 dot, sigmoid, write 4 outputs ----
    if (tid < 128) {
        int e = tid >> 5, j = lane;
        float x3 = b3[j] + sP2[e * 64 + j] + sP2[e * 64 + 32 + j];
        x3 = fmaxf(x3, 0.f);
        float v = x3 * W4[j];
        #pragma unroll
        for (int off = 16; off; off >>= 1) v += __shfl_xor_sync(0xffffffffu, v, off);
        if (j == 0) out[b0 + e] = 1.f / (1.f + __expf(-(v + b4[0])));
    }
}

extern "C" void kernel_launch(void* const* d_in, const int* in_sizes, int n_in,
                              void* d_out, int out_size)
{
    (void)in_sizes; (void)n_in; (void)out_size;

    devfeat_kernel<<<(N_DEV + 7) / 8, NTHREADS>>>(
        (const float*)d_in[2],   // device_cont
        (const int*)  d_in[3],   // device_cat
        (const float*)d_in[9],   // de0
        (const float*)d_in[10]); // de1

    prep_kernel<<<1, NTHREADS>>>(
        (const float*)d_in[11],  // Wc
        (const float*)d_in[12],  // bc
        (const float*)d_in[13],  // Wd
        (const float*)d_in[14],  // bd
        (const float*)d_in[15],  // aW
        (const float*)d_in[16],  // ab
        (const float*)d_in[17],  // W1
        (const float*)d_in[18],  // b1
        (const float*)d_in[19],  // W2
        (const float*)d_in[20]); // b2

    gat_kernel<<<N_B / NB4, NTHREADS>>>(
        (const float*)d_in[0],   // combin_cont
        (const int*)  d_in[1],   // combin_cat
        (const int*)  d_in[4],   // combin_idx
        (const int*)  d_in[5],   // device_idx
        (const int*)  d_in[6],   // neighbor_idx
        (const float*)d_in[7],   // ce0
        (const float*)d_in[8],   // ce1
        (const float*)d_in[14],  // bd
        (const float*)d_in[21],  // W3
        (const float*)d_in[22],  // b3
        (const float*)d_in[23],  // W4
        (const float*)d_in[24],  // b4
        (float*)d_out);
}